// round 6
// baseline (speedup 1.0000x reference)
#include <cuda_runtime.h>
#include <cuda_bf16.h>
#include <cstdint>

// Problem constants: B=2, S=2048, D=1024, H=16, HD=64
#define BB 2
#define SS 2048
#define DD 1024
#define NH 16
#define HD 64

// ---------------------------------------------------------------------------
// mma.sync / ldmatrix / cp.async helpers (plain PTX, no sm_103a-gated features)
// ---------------------------------------------------------------------------
__device__ __forceinline__ uint32_t smem_u32(const void* p) {
    uint32_t a;
    asm("{ .reg .u64 t; cvta.to.shared.u64 t, %1; cvt.u32.u64 %0, t; }"
        : "=r"(a) : "l"(p));
    return a;
}
__device__ __forceinline__ void ldsm_x4(uint32_t* r, uint32_t addr) {
    asm volatile("ldmatrix.sync.aligned.m8n8.x4.shared.b16 {%0,%1,%2,%3}, [%4];"
        : "=r"(r[0]), "=r"(r[1]), "=r"(r[2]), "=r"(r[3]) : "r"(addr));
}
__device__ __forceinline__ void ldsm_x4_trans(uint32_t* r, uint32_t addr) {
    asm volatile("ldmatrix.sync.aligned.m8n8.x4.trans.shared.b16 {%0,%1,%2,%3}, [%4];"
        : "=r"(r[0]), "=r"(r[1]), "=r"(r[2]), "=r"(r[3]) : "r"(addr));
}
__device__ __forceinline__ void mma16816(float* c, const uint32_t* a,
                                         uint32_t b0, uint32_t b1) {
    asm volatile(
        "mma.sync.aligned.m16n8k16.row.col.f32.bf16.bf16.f32 "
        "{%0,%1,%2,%3}, {%4,%5,%6,%7}, {%8,%9}, {%0,%1,%2,%3};"
        : "+f"(c[0]), "+f"(c[1]), "+f"(c[2]), "+f"(c[3])
        : "r"(a[0]), "r"(a[1]), "r"(a[2]), "r"(a[3]), "r"(b0), "r"(b1));
}
__device__ __forceinline__ void cp_async16(uint32_t dst, const void* src) {
    asm volatile("cp.async.cg.shared.global [%0], [%1], 16;"
        :: "r"(dst), "l"(src));
}
#define CP_COMMIT() asm volatile("cp.async.commit_group;" ::: "memory")
#define CP_WAIT(n)  asm volatile("cp.async.wait_group %0;" :: "n"(n) : "memory")

// pack: low half = first arg, high half = second arg
__device__ __forceinline__ uint32_t pack_bf16x2(float lo_elem, float hi_elem) {
    uint32_t r;
    asm("cvt.rn.bf16x2.f32 %0, %1, %2;" : "=r"(r) : "f"(hi_elem), "f"(lo_elem));
    return r;
}
__device__ __forceinline__ float bf16_round(float v) {
    return __bfloat162float(__float2bfloat16(v));
}

// ---------------------------------------------------------------------------
// Scratch (__device__ globals; allocation-free rule)
// ---------------------------------------------------------------------------
__device__ __nv_bfloat16 g_xhi[(size_t)BB * SS * DD];
__device__ __nv_bfloat16 g_xlo[(size_t)BB * SS * DD];
__device__ __nv_bfloat16 g_qkvh[(size_t)BB * SS * 3 * DD];
__device__ __nv_bfloat16 g_qkvl[(size_t)BB * SS * 3 * DD];
__device__ __nv_bfloat16 g_yh[(size_t)BB * SS * DD];
__device__ __nv_bfloat16 g_yl[(size_t)BB * SS * DD];
__device__ __nv_bfloat16 g_wqkvT_hi[(size_t)3 * DD * DD];
__device__ __nv_bfloat16 g_wqkvT_lo[(size_t)3 * DD * DD];
__device__ __nv_bfloat16 g_wprojT_hi[(size_t)DD * DD];
__device__ __nv_bfloat16 g_wprojT_lo[(size_t)DD * DD];

// ---------------------------------------------------------------------------
// Elementwise fp32 -> bf16 hi/lo split, vectorized (4 elems/thread)
// ---------------------------------------------------------------------------
__global__ __launch_bounds__(256) void split_kernel(
    const float4* __restrict__ in, uint32_t* __restrict__ hi,
    uint32_t* __restrict__ lo, int n4)
{
    int i = blockIdx.x * 256 + threadIdx.x;
    if (i < n4) {
        float4 v = in[i];
        float h0 = bf16_round(v.x), h1 = bf16_round(v.y);
        float h2 = bf16_round(v.z), h3 = bf16_round(v.w);
        hi[i * 2 + 0] = pack_bf16x2(h0, h1);
        hi[i * 2 + 1] = pack_bf16x2(h2, h3);
        lo[i * 2 + 0] = pack_bf16x2(v.x - h0, v.y - h1);
        lo[i * 2 + 1] = pack_bf16x2(v.z - h2, v.w - h3);
    }
}

// ---------------------------------------------------------------------------
// Transpose + split: in [K,N] fp32 -> hiT/loT [N,K] bf16 (K-major)
// ---------------------------------------------------------------------------
__global__ __launch_bounds__(256) void transpose_split_kernel(
    const float* __restrict__ in, __nv_bfloat16* __restrict__ hiT,
    __nv_bfloat16* __restrict__ loT, int K, int N)
{
    __shared__ float t[32][33];
    const int tx = threadIdx.x & 31;
    const int ty = threadIdx.x >> 5;
    const int n0 = blockIdx.x * 32;
    const int k0 = blockIdx.y * 32;
    #pragma unroll
    for (int i = 0; i < 4; i++) {
        int k = k0 + ty + i * 8;
        t[ty + i * 8][tx] = in[(size_t)k * N + n0 + tx];
    }
    __syncthreads();
    #pragma unroll
    for (int i = 0; i < 4; i++) {
        int n = n0 + ty + i * 8;
        int k = k0 + tx;
        float v = t[tx][ty + i * 8];
        __nv_bfloat16 h = __float2bfloat16(v);
        hiT[(size_t)n * K + k] = h;
        loT[(size_t)n * K + k] = __float2bfloat16(v - __bfloat162float(h));
    }
}

// ---------------------------------------------------------------------------
// bf16-split GEMM via mma.sync, cp.async 2-stage, ONE barrier per K-chunk.
// Loop order: wait(0) -> sync -> issue(kc+1) -> compute(kc). The sync at
// iter kc+1 orders all warps' compute(kc) reads before load(kc+2) clobbers.
// C = (Ahi+Alo)[M,K] @ (Bhi+Blo)[N,K]^T ; D = hh + hl + lh, fp32 accumulate.
// CTA 128x128, BK=32, 256 threads (8 warps 2x4), warp tile 64x32.
// ---------------------------------------------------------------------------
#define ROWB 80
#define GSTAGE 40960
#define SA_HI 0
#define SA_LO 10240
#define SB_HI 20480
#define SB_LO 30720
#define GEMM_SMEM (2 * GSTAGE)

__global__ __launch_bounds__(256, 2) void mma_gemm_kernel(
    const __nv_bfloat16* __restrict__ Ahi, const __nv_bfloat16* __restrict__ Alo,
    const __nv_bfloat16* __restrict__ Bhi, const __nv_bfloat16* __restrict__ Blo,
    float* __restrict__ Cf, __nv_bfloat16* __restrict__ Chi,
    __nv_bfloat16* __restrict__ Clo, int Ntot, int K)
{
    extern __shared__ __align__(16) char sm[];
    const uint32_t smb = smem_u32(sm);

    const int tid = threadIdx.x;
    const int wid = tid >> 5;
    const int lane = tid & 31;
    const int warp_m = wid >> 2;
    const int warp_n = wid & 3;
    const int row0 = blockIdx.y * 128;
    const int col0 = blockIdx.x * 128;

    const uint32_t a_lane_off = (uint32_t)(lane & 15) * ROWB + ((lane >> 4) & 1) * 16;
    const uint32_t b_lane_off = ((uint32_t)((lane & 7) + ((lane >> 4) & 1) * 8)) * ROWB
                              + ((lane >> 3) & 1) * 16;

    const int l_r0 = tid >> 2, l_c = (tid & 3);
    const uint32_t l_dst0 = (uint32_t)l_r0 * ROWB + (uint32_t)l_c * 16;
    const uint32_t l_dst1 = (uint32_t)(l_r0 + 64) * ROWB + (uint32_t)l_c * 16;

    auto load_stage = [&](int kc, int st) {
        const int k0 = kc << 5;
        const uint32_t base = smb + (uint32_t)st * GSTAGE;
        size_t a0 = (size_t)(row0 + l_r0) * K + k0 + l_c * 8;
        size_t b0 = (size_t)(col0 + l_r0) * K + k0 + l_c * 8;
        size_t a1 = a0 + (size_t)64 * K;
        size_t b1 = b0 + (size_t)64 * K;
        cp_async16(base + SA_HI + l_dst0, Ahi + a0);
        cp_async16(base + SA_HI + l_dst1, Ahi + a1);
        cp_async16(base + SA_LO + l_dst0, Alo + a0);
        cp_async16(base + SA_LO + l_dst1, Alo + a1);
        cp_async16(base + SB_HI + l_dst0, Bhi + b0);
        cp_async16(base + SB_HI + l_dst1, Bhi + b1);
        cp_async16(base + SB_LO + l_dst0, Blo + b0);
        cp_async16(base + SB_LO + l_dst1, Blo + b1);
    };

    float acc[4][4][4] = {};

    const int nchunks = K >> 5;
    load_stage(0, 0);
    CP_COMMIT();

    for (int kc = 0; kc < nchunks; kc++) {
        CP_WAIT(0);
        __syncthreads();
        if (kc + 1 < nchunks) {
            load_stage(kc + 1, (kc + 1) & 1);
            CP_COMMIT();
        }

        const uint32_t stb = smb + (uint32_t)(kc & 1) * GSTAGE;
        #pragma unroll
        for (int ks = 0; ks < 2; ks++) {
            const uint32_t koff = (uint32_t)ks * 32;
            uint32_t ah[4][4], al[4][4], bh[2][4], bl[2][4];
            #pragma unroll
            for (int pr = 0; pr < 2; pr++) {
                uint32_t bb = (uint32_t)(warp_n * 32 + pr * 16) * ROWB + koff + b_lane_off;
                ldsm_x4(bh[pr], stb + SB_HI + bb);
                ldsm_x4(bl[pr], stb + SB_LO + bb);
            }
            #pragma unroll
            for (int mm = 0; mm < 4; mm++) {
                uint32_t ab = (uint32_t)(warp_m * 64 + mm * 16) * ROWB + koff + a_lane_off;
                ldsm_x4(ah[mm], stb + SA_HI + ab);
                ldsm_x4(al[mm], stb + SA_LO + ab);
            }
            #pragma unroll
            for (int mm = 0; mm < 4; mm++) {
                #pragma unroll
                for (int nn = 0; nn < 4; nn++) {
                    const int pr = nn >> 1, sb2 = (nn & 1) * 2;
                    mma16816(acc[mm][nn], ah[mm], bh[pr][sb2], bh[pr][sb2 + 1]);
                    mma16816(acc[mm][nn], ah[mm], bl[pr][sb2], bl[pr][sb2 + 1]);
                    mma16816(acc[mm][nn], al[mm], bh[pr][sb2], bh[pr][sb2 + 1]);
                }
            }
        }
    }

    const int g = lane >> 2, tq = lane & 3;
    #pragma unroll
    for (int mm = 0; mm < 4; mm++) {
        #pragma unroll
        for (int nn = 0; nn < 4; nn++) {
            int row = row0 + warp_m * 64 + mm * 16 + g;
            int col = col0 + warp_n * 32 + nn * 8 + tq * 2;
            if (Chi) {
                #pragma unroll
                for (int half = 0; half < 2; half++) {
                    float v0 = acc[mm][nn][half * 2 + 0];
                    float v1 = acc[mm][nn][half * 2 + 1];
                    float h0 = bf16_round(v0), h1 = bf16_round(v1);
                    size_t idx = (size_t)(row + half * 8) * Ntot + col;
                    *reinterpret_cast<uint32_t*>(Chi + idx) = pack_bf16x2(h0, h1);
                    *reinterpret_cast<uint32_t*>(Clo + idx) = pack_bf16x2(v0 - h0, v1 - h1);
                }
            } else {
                *reinterpret_cast<float2*>(&Cf[(size_t)row * Ntot + col]) =
                    make_float2(acc[mm][nn][0], acc[mm][nn][1]);
                *reinterpret_cast<float2*>(&Cf[(size_t)(row + 8) * Ntot + col]) =
                    make_float2(acc[mm][nn][2], acc[mm][nn][3]);
            }
        }
    }
}

// ---------------------------------------------------------------------------
// Flash attention via mma.sync, bf16 hi/lo split, cp.async 2-stage KV
// pipeline with ONE barrier per j-block (same ordering as the GEMM).
// CTA = 128 q-rows x one (b,h). 8 warps x 16 q-rows. j-blocks of 64.
// Warps fully above the diagonal skip the block's compute.
// ---------------------------------------------------------------------------
#define AROWB 144
#define SQ_HI 0
#define SQ_LO 18432
#define AKV0 36864
#define ASTAGE 36864
#define AK_HI 0
#define AK_LO 9216
#define AV_HI 18432
#define AV_LO 27648
#define ATTN_SMEM (AKV0 + 2 * ASTAGE)

__global__ __launch_bounds__(256) void mma_attn_kernel(
    const __nv_bfloat16* __restrict__ qkvh, const __nv_bfloat16* __restrict__ qkvl,
    __nv_bfloat16* __restrict__ yh, __nv_bfloat16* __restrict__ yl)
{
    extern __shared__ __align__(16) char sm[];
    const uint32_t smb = smem_u32(sm);
    const int tid = threadIdx.x;
    const int w = tid >> 5;
    const int lane = tid & 31;
    const int g = lane >> 2, tq = lane & 3;
    const int qb = blockIdx.x;
    const int bh = blockIdx.y;
    const int b = bh >> 4, h = bh & 15;

    const int kv_r0 = tid >> 3, kv_c = tid & 7;
    const uint32_t kv_dst0 = (uint32_t)kv_r0 * AROWB + (uint32_t)kv_c * 16;
    const uint32_t kv_dst1 = (uint32_t)(kv_r0 + 32) * AROWB + (uint32_t)kv_c * 16;

    auto load_kv = [&](int jb, int st) {
        const int j0 = jb * 64;
        const uint32_t base = smb + AKV0 + (uint32_t)st * ASTAGE;
        size_t k0s = ((size_t)(b * SS + j0 + kv_r0)) * (3 * DD) + DD + h * HD + kv_c * 8;
        size_t k1s = k0s + (size_t)32 * (3 * DD);
        cp_async16(base + AK_HI + kv_dst0, qkvh + k0s);
        cp_async16(base + AK_HI + kv_dst1, qkvh + k1s);
        cp_async16(base + AK_LO + kv_dst0, qkvl + k0s);
        cp_async16(base + AK_LO + kv_dst1, qkvl + k1s);
        cp_async16(base + AV_HI + kv_dst0, qkvh + k0s + DD);
        cp_async16(base + AV_HI + kv_dst1, qkvh + k1s + DD);
        cp_async16(base + AV_LO + kv_dst0, qkvl + k0s + DD);
        cp_async16(base + AV_LO + kv_dst1, qkvl + k1s + DD);
    };

    // Stage Q tiles (group 0), prefetch KV block 0 (group 1)
    #pragma unroll
    for (int i = 0; i < 4; i++) {
        int u = tid + i * 256;
        int r = u >> 3, c = u & 7;
        uint32_t dst = (uint32_t)r * AROWB + (uint32_t)c * 16;
        size_t src = ((size_t)(b * SS + qb * 128 + r)) * (3 * DD) + h * HD + c * 8;
        cp_async16(smb + SQ_HI + dst, qkvh + src);
        cp_async16(smb + SQ_LO + dst, qkvl + src);
    }
    CP_COMMIT();
    load_kv(0, 0);
    CP_COMMIT();

    CP_WAIT(1);          // Q resident
    __syncthreads();

    const uint32_t a_off = (uint32_t)(lane & 15) * AROWB + ((lane >> 4) & 1) * 16;
    uint32_t qfh[4][4], qfl[4][4];
    #pragma unroll
    for (int t = 0; t < 4; t++) {
        uint32_t base = (uint32_t)(w * 16) * AROWB + (uint32_t)t * 32 + a_off;
        ldsm_x4(qfh[t], smb + SQ_HI + base);
        ldsm_x4(qfl[t], smb + SQ_LO + base);
    }

    float yacc[8][4] = {};
    float m0 = -1e30f, m1 = -1e30f, l0 = 0.0f, l1 = 0.0f;

    const uint32_t b_off = ((uint32_t)((lane & 7) + ((lane >> 4) & 1) * 8)) * AROWB
                         + ((lane >> 3) & 1) * 16;
    const uint32_t v_off = (uint32_t)(lane & 15) * AROWB + ((lane >> 4) & 1) * 16;
    const int rowbase = qb * 128 + w * 16;

    const int njb = 2 * qb + 2;
    for (int jb = 0; jb < njb; jb++) {
        const int j0 = jb * 64;
        CP_WAIT(0);
        __syncthreads();
        if (jb + 1 < njb) {
            load_kv(jb + 1, (jb + 1) & 1);
            CP_COMMIT();
        }

        if (j0 <= rowbase + 15) {   // strip not fully above diagonal
            const uint32_t kvb = smb + AKV0 + (uint32_t)(jb & 1) * ASTAGE;

            // S = Q K^T (hi*hi + hi*lo + lo*hi)
            float sacc[8][4] = {};
            #pragma unroll
            for (int t = 0; t < 4; t++) {
                uint32_t kh[4][4], kl[4][4];
                #pragma unroll
                for (int pr = 0; pr < 4; pr++) {
                    uint32_t ad = (uint32_t)(pr * 16) * AROWB + (uint32_t)t * 32 + b_off;
                    ldsm_x4(kh[pr], kvb + AK_HI + ad);
                    ldsm_x4(kl[pr], kvb + AK_LO + ad);
                }
                #pragma unroll
                for (int nn = 0; nn < 8; nn++) {
                    const int pr = nn >> 1, s2 = (nn & 1) * 2;
                    mma16816(sacc[nn], qfh[t], kh[pr][s2], kh[pr][s2 + 1]);
                    mma16816(sacc[nn], qfh[t], kl[pr][s2], kl[pr][s2 + 1]);
                    mma16816(sacc[nn], qfl[t], kh[pr][s2], kh[pr][s2 + 1]);
                }
            }

            #pragma unroll
            for (int nn = 0; nn < 8; nn++)
                #pragma unroll
                for (int e = 0; e < 4; e++) sacc[nn][e] *= 0.125f;

            if (j0 + 63 > rowbase) {
                const int r0 = rowbase + g, r1 = r0 + 8;
                #pragma unroll
                for (int nn = 0; nn < 8; nn++) {
                    int col = j0 + nn * 8 + 2 * tq;
                    if (col > r0)     sacc[nn][0] = -1e30f;
                    if (col + 1 > r0) sacc[nn][1] = -1e30f;
                    if (col > r1)     sacc[nn][2] = -1e30f;
                    if (col + 1 > r1) sacc[nn][3] = -1e30f;
                }
            }

            // Online softmax (rows g, g+8)
            float mx0 = -1e30f, mx1 = -1e30f;
            #pragma unroll
            for (int nn = 0; nn < 8; nn++) {
                mx0 = fmaxf(mx0, fmaxf(sacc[nn][0], sacc[nn][1]));
                mx1 = fmaxf(mx1, fmaxf(sacc[nn][2], sacc[nn][3]));
            }
            mx0 = fmaxf(mx0, __shfl_xor_sync(0xffffffffu, mx0, 1));
            mx0 = fmaxf(mx0, __shfl_xor_sync(0xffffffffu, mx0, 2));
            mx1 = fmaxf(mx1, __shfl_xor_sync(0xffffffffu, mx1, 1));
            mx1 = fmaxf(mx1, __shfl_xor_sync(0xffffffffu, mx1, 2));

            float mn0 = fmaxf(m0, mx0), mn1 = fmaxf(m1, mx1);
            float f0 = __expf(m0 - mn0), f1 = __expf(m1 - mn1);
            m0 = mn0; m1 = mn1;

            float p[8][4];
            float ps0 = 0.0f, ps1 = 0.0f;
            #pragma unroll
            for (int nn = 0; nn < 8; nn++) {
                p[nn][0] = __expf(sacc[nn][0] - m0);
                p[nn][1] = __expf(sacc[nn][1] - m0);
                p[nn][2] = __expf(sacc[nn][2] - m1);
                p[nn][3] = __expf(sacc[nn][3] - m1);
                ps0 += p[nn][0] + p[nn][1];
                ps1 += p[nn][2] + p[nn][3];
            }
            ps0 += __shfl_xor_sync(0xffffffffu, ps0, 1);
            ps0 += __shfl_xor_sync(0xffffffffu, ps0, 2);
            ps1 += __shfl_xor_sync(0xffffffffu, ps1, 1);
            ps1 += __shfl_xor_sync(0xffffffffu, ps1, 2);
            l0 = l0 * f0 + ps0;
            l1 = l1 * f1 + ps1;

            #pragma unroll
            for (int nn = 0; nn < 8; nn++) {
                yacc[nn][0] *= f0; yacc[nn][1] *= f0;
                yacc[nn][2] *= f1; yacc[nn][3] *= f1;
            }

            // Pack P into A-fragments (hi/lo)
            uint32_t ph[4][4], pl[4][4];
            #pragma unroll
            for (int t = 0; t < 4; t++) {
                #pragma unroll
                for (int q2 = 0; q2 < 2; q2++) {
                    const float* pp = p[2 * t + q2];
                    float h0 = bf16_round(pp[0]), h1 = bf16_round(pp[1]);
                    float h2 = bf16_round(pp[2]), h3 = bf16_round(pp[3]);
                    ph[t][2 * q2 + 0] = pack_bf16x2(h0, h1);
                    ph[t][2 * q2 + 1] = pack_bf16x2(h2, h3);
                    pl[t][2 * q2 + 0] = pack_bf16x2(pp[0] - h0, pp[1] - h1);
                    pl[t][2 * q2 + 1] = pack_bf16x2(pp[2] - h2, pp[3] - h3);
                }
            }

            // y += P V (V via ldmatrix.trans)
            #pragma unroll
            for (int t = 0; t < 4; t++) {
                #pragma unroll
                for (int d16 = 0; d16 < 4; d16++) {
                    uint32_t vh[4], vl[4];
                    uint32_t ad = (uint32_t)(16 * t) * AROWB + (uint32_t)d16 * 32 + v_off;
                    ldsm_x4_trans(vh, kvb + AV_HI + ad);
                    ldsm_x4_trans(vl, kvb + AV_LO + ad);
                    mma16816(yacc[2 * d16 + 0], ph[t], vh[0], vh[1]);
                    mma16816(yacc[2 * d16 + 0], ph[t], vl[0], vl[1]);
                    mma16816(yacc[2 * d16 + 0], pl[t], vh[0], vh[1]);
                    mma16816(yacc[2 * d16 + 1], ph[t], vh[2], vh[3]);
                    mma16816(yacc[2 * d16 + 1], ph[t], vl[2], vl[3]);
                    mma16816(yacc[2 * d16 + 1], pl[t], vh[2], vh[3]);
                }
            }
        }
    }

    // Epilogue: y /= l, write bf16 hi/lo
    const float i0 = 1.0f / l0, i1 = 1.0f / l1;
    const int grow0 = b * SS + qb * 128 + w * 16 + g;
    #pragma unroll
    for (int nn = 0; nn < 8; nn++) {
        int col = h * HD + nn * 8 + 2 * tq;
        float v0 = yacc[nn][0] * i0, v1 = yacc[nn][1] * i0;
        float v2 = yacc[nn][2] * i1, v3 = yacc[nn][3] * i1;
        float h0 = bf16_round(v0), h1 = bf16_round(v1);
        float h2 = bf16_round(v2), h3 = bf16_round(v3);
        size_t idx0 = (size_t)grow0 * DD + col;
        size_t idx1 = (size_t)(grow0 + 8) * DD + col;
        *reinterpret_cast<uint32_t*>(yh + idx0) = pack_bf16x2(h0, h1);
        *reinterpret_cast<uint32_t*>(yl + idx0) = pack_bf16x2(v0 - h0, v1 - h1);
        *reinterpret_cast<uint32_t*>(yh + idx1) = pack_bf16x2(h2, h3);
        *reinterpret_cast<uint32_t*>(yl + idx1) = pack_bf16x2(v2 - h2, v3 - h3);
    }
}

// ---------------------------------------------------------------------------
// Launch
// ---------------------------------------------------------------------------
extern "C" void kernel_launch(void* const* d_in, const int* in_sizes, int n_in,
                              void* d_out, int out_size)
{
    const float* x      = (const float*)d_in[0];
    const float* w_qkv  = (const float*)d_in[1];
    const float* w_proj = (const float*)d_in[2];
    float* out = (float*)d_out;

    __nv_bfloat16 *xhi, *xlo, *qkvh, *qkvl, *yh, *yl;
    __nv_bfloat16 *wqT_hi, *wqT_lo, *wpT_hi, *wpT_lo;
    cudaGetSymbolAddress((void**)&xhi, g_xhi);
    cudaGetSymbolAddress((void**)&xlo, g_xlo);
    cudaGetSymbolAddress((void**)&qkvh, g_qkvh);
    cudaGetSymbolAddress((void**)&qkvl, g_qkvl);
    cudaGetSymbolAddress((void**)&yh, g_yh);
    cudaGetSymbolAddress((void**)&yl, g_yl);
    cudaGetSymbolAddress((void**)&wqT_hi, g_wqkvT_hi);
    cudaGetSymbolAddress((void**)&wqT_lo, g_wqkvT_lo);
    cudaGetSymbolAddress((void**)&wpT_hi, g_wprojT_hi);
    cudaGetSymbolAddress((void**)&wpT_lo, g_wprojT_lo);

    cudaFuncSetAttribute(mma_gemm_kernel,
                         cudaFuncAttributeMaxDynamicSharedMemorySize, GEMM_SMEM);
    cudaFuncSetAttribute(mma_attn_kernel,
                         cudaFuncAttributeMaxDynamicSharedMemorySize, ATTN_SMEM);

    const int M = BB * SS;
    const int nElemX = M * DD;

    split_kernel<<<nElemX / 1024, 256>>>(
        (const float4*)x, (uint32_t*)xhi, (uint32_t*)xlo, nElemX / 4);
    transpose_split_kernel<<<dim3(3 * DD / 32, DD / 32), 256>>>(w_qkv, wqT_hi, wqT_lo, DD, 3 * DD);
    transpose_split_kernel<<<dim3(DD / 32, DD / 32), 256>>>(w_proj, wpT_hi, wpT_lo, DD, DD);

    mma_gemm_kernel<<<dim3(3 * DD / 128, M / 128), 256, GEMM_SMEM>>>(
        xhi, xlo, wqT_hi, wqT_lo, nullptr, qkvh, qkvl, 3 * DD, DD);

    mma_attn_kernel<<<dim3(SS / 128, BB * NH), 256, ATTN_SMEM>>>(qkvh, qkvl, yh, yl);

    mma_gemm_kernel<<<dim3(DD / 128, M / 128), 256, GEMM_SMEM>>>(
        yh, yl, wpT_hi, wpT_lo, out, nullptr, nullptr, DD, DD);
}

// round 7
// speedup vs baseline: 1.0013x; 1.0013x over previous
#include <cuda_runtime.h>
#include <cuda_bf16.h>
#include <cstdint>

// Problem constants: B=2, S=2048, D=1024, H=16, HD=64
#define BB 2
#define SS 2048
#define DD 1024
#define NH 16
#define HD 64

// ---------------------------------------------------------------------------
// mma.sync / ldmatrix / cp.async helpers (plain PTX, no sm_103a-gated features)
// ---------------------------------------------------------------------------
__device__ __forceinline__ uint32_t smem_u32(const void* p) {
    uint32_t a;
    asm("{ .reg .u64 t; cvta.to.shared.u64 t, %1; cvt.u32.u64 %0, t; }"
        : "=r"(a) : "l"(p));
    return a;
}
__device__ __forceinline__ void ldsm_x4(uint32_t* r, uint32_t addr) {
    asm volatile("ldmatrix.sync.aligned.m8n8.x4.shared.b16 {%0,%1,%2,%3}, [%4];"
        : "=r"(r[0]), "=r"(r[1]), "=r"(r[2]), "=r"(r[3]) : "r"(addr));
}
__device__ __forceinline__ void ldsm_x4_trans(uint32_t* r, uint32_t addr) {
    asm volatile("ldmatrix.sync.aligned.m8n8.x4.trans.shared.b16 {%0,%1,%2,%3}, [%4];"
        : "=r"(r[0]), "=r"(r[1]), "=r"(r[2]), "=r"(r[3]) : "r"(addr));
}
// NOT volatile: pure register op -> ptxas may interleave independent mmas
// (breaking the same-accumulator RAW chains that capped tensor% at ~52).
__device__ __forceinline__ void mma16816(float* c, const uint32_t* a,
                                         uint32_t b0, uint32_t b1) {
    asm("mma.sync.aligned.m16n8k16.row.col.f32.bf16.bf16.f32 "
        "{%0,%1,%2,%3}, {%4,%5,%6,%7}, {%8,%9}, {%0,%1,%2,%3};"
        : "+f"(c[0]), "+f"(c[1]), "+f"(c[2]), "+f"(c[3])
        : "r"(a[0]), "r"(a[1]), "r"(a[2]), "r"(a[3]), "r"(b0), "r"(b1));
}
__device__ __forceinline__ void cp_async16(uint32_t dst, const void* src) {
    asm volatile("cp.async.cg.shared.global [%0], [%1], 16;"
        :: "r"(dst), "l"(src));
}
#define CP_COMMIT() asm volatile("cp.async.commit_group;" ::: "memory")
#define CP_WAIT(n)  asm volatile("cp.async.wait_group %0;" :: "n"(n) : "memory")

// pack: low half = first arg, high half = second arg
__device__ __forceinline__ uint32_t pack_bf16x2(float lo_elem, float hi_elem) {
    uint32_t r;
    asm("cvt.rn.bf16x2.f32 %0, %1, %2;" : "=r"(r) : "f"(hi_elem), "f"(lo_elem));
    return r;
}
__device__ __forceinline__ float bf16_round(float v) {
    return __bfloat162float(__float2bfloat16(v));
}

// ---------------------------------------------------------------------------
// Scratch (__device__ globals; allocation-free rule)
// ---------------------------------------------------------------------------
__device__ __nv_bfloat16 g_xhi[(size_t)BB * SS * DD];
__device__ __nv_bfloat16 g_xlo[(size_t)BB * SS * DD];
__device__ __nv_bfloat16 g_qkvh[(size_t)BB * SS * 3 * DD];
__device__ __nv_bfloat16 g_qkvl[(size_t)BB * SS * 3 * DD];
__device__ __nv_bfloat16 g_yh[(size_t)BB * SS * DD];
__device__ __nv_bfloat16 g_yl[(size_t)BB * SS * DD];
__device__ __nv_bfloat16 g_wqkvT_hi[(size_t)3 * DD * DD];
__device__ __nv_bfloat16 g_wqkvT_lo[(size_t)3 * DD * DD];
__device__ __nv_bfloat16 g_wprojT_hi[(size_t)DD * DD];
__device__ __nv_bfloat16 g_wprojT_lo[(size_t)DD * DD];

// ---------------------------------------------------------------------------
// Elementwise fp32 -> bf16 hi/lo split, vectorized (4 elems/thread)
// ---------------------------------------------------------------------------
__global__ __launch_bounds__(256) void split_kernel(
    const float4* __restrict__ in, uint32_t* __restrict__ hi,
    uint32_t* __restrict__ lo, int n4)
{
    int i = blockIdx.x * 256 + threadIdx.x;
    if (i < n4) {
        float4 v = in[i];
        float h0 = bf16_round(v.x), h1 = bf16_round(v.y);
        float h2 = bf16_round(v.z), h3 = bf16_round(v.w);
        hi[i * 2 + 0] = pack_bf16x2(h0, h1);
        hi[i * 2 + 1] = pack_bf16x2(h2, h3);
        lo[i * 2 + 0] = pack_bf16x2(v.x - h0, v.y - h1);
        lo[i * 2 + 1] = pack_bf16x2(v.z - h2, v.w - h3);
    }
}

// ---------------------------------------------------------------------------
// Transpose + split: in [K,N] fp32 -> hiT/loT [N,K] bf16 (K-major)
// ---------------------------------------------------------------------------
__global__ __launch_bounds__(256) void transpose_split_kernel(
    const float* __restrict__ in, __nv_bfloat16* __restrict__ hiT,
    __nv_bfloat16* __restrict__ loT, int K, int N)
{
    __shared__ float t[32][33];
    const int tx = threadIdx.x & 31;
    const int ty = threadIdx.x >> 5;
    const int n0 = blockIdx.x * 32;
    const int k0 = blockIdx.y * 32;
    #pragma unroll
    for (int i = 0; i < 4; i++) {
        int k = k0 + ty + i * 8;
        t[ty + i * 8][tx] = in[(size_t)k * N + n0 + tx];
    }
    __syncthreads();
    #pragma unroll
    for (int i = 0; i < 4; i++) {
        int n = n0 + ty + i * 8;
        int k = k0 + tx;
        float v = t[tx][ty + i * 8];
        __nv_bfloat16 h = __float2bfloat16(v);
        hiT[(size_t)n * K + k] = h;
        loT[(size_t)n * K + k] = __float2bfloat16(v - __bfloat162float(h));
    }
}

// ---------------------------------------------------------------------------
// bf16-split GEMM via mma.sync, cp.async 2-stage, one barrier per K-chunk.
// Split terms issued TERM-OUTER: all 16 accumulators get hh, then hl, then
// lh -> dependency distance 16 (was 1), hiding HMMA result latency.
// C = (Ahi+Alo)[M,K] @ (Bhi+Blo)[N,K]^T ; fp32 accumulate.
// CTA 128x128, BK=32, 256 threads (8 warps 2x4), warp tile 64x32.
// ---------------------------------------------------------------------------
#define ROWB 80
#define GSTAGE 40960
#define SA_HI 0
#define SA_LO 10240
#define SB_HI 20480
#define SB_LO 30720
#define GEMM_SMEM (2 * GSTAGE)

__global__ __launch_bounds__(256, 2) void mma_gemm_kernel(
    const __nv_bfloat16* __restrict__ Ahi, const __nv_bfloat16* __restrict__ Alo,
    const __nv_bfloat16* __restrict__ Bhi, const __nv_bfloat16* __restrict__ Blo,
    float* __restrict__ Cf, __nv_bfloat16* __restrict__ Chi,
    __nv_bfloat16* __restrict__ Clo, int Ntot, int K)
{
    extern __shared__ __align__(16) char sm[];
    const uint32_t smb = smem_u32(sm);

    const int tid = threadIdx.x;
    const int wid = tid >> 5;
    const int lane = tid & 31;
    const int warp_m = wid >> 2;
    const int warp_n = wid & 3;
    const int row0 = blockIdx.y * 128;
    const int col0 = blockIdx.x * 128;

    const uint32_t a_lane_off = (uint32_t)(lane & 15) * ROWB + ((lane >> 4) & 1) * 16;
    const uint32_t b_lane_off = ((uint32_t)((lane & 7) + ((lane >> 4) & 1) * 8)) * ROWB
                              + ((lane >> 3) & 1) * 16;

    const int l_r0 = tid >> 2, l_c = (tid & 3);
    const uint32_t l_dst0 = (uint32_t)l_r0 * ROWB + (uint32_t)l_c * 16;
    const uint32_t l_dst1 = (uint32_t)(l_r0 + 64) * ROWB + (uint32_t)l_c * 16;

    auto load_stage = [&](int kc, int st) {
        const int k0 = kc << 5;
        const uint32_t base = smb + (uint32_t)st * GSTAGE;
        size_t a0 = (size_t)(row0 + l_r0) * K + k0 + l_c * 8;
        size_t b0 = (size_t)(col0 + l_r0) * K + k0 + l_c * 8;
        size_t a1 = a0 + (size_t)64 * K;
        size_t b1 = b0 + (size_t)64 * K;
        cp_async16(base + SA_HI + l_dst0, Ahi + a0);
        cp_async16(base + SA_HI + l_dst1, Ahi + a1);
        cp_async16(base + SA_LO + l_dst0, Alo + a0);
        cp_async16(base + SA_LO + l_dst1, Alo + a1);
        cp_async16(base + SB_HI + l_dst0, Bhi + b0);
        cp_async16(base + SB_HI + l_dst1, Bhi + b1);
        cp_async16(base + SB_LO + l_dst0, Blo + b0);
        cp_async16(base + SB_LO + l_dst1, Blo + b1);
    };

    float acc[4][4][4] = {};

    const int nchunks = K >> 5;
    load_stage(0, 0);
    CP_COMMIT();

    for (int kc = 0; kc < nchunks; kc++) {
        CP_WAIT(0);
        __syncthreads();
        if (kc + 1 < nchunks) {
            load_stage(kc + 1, (kc + 1) & 1);
            CP_COMMIT();
        }

        const uint32_t stb = smb + (uint32_t)(kc & 1) * GSTAGE;
        #pragma unroll
        for (int ks = 0; ks < 2; ks++) {
            const uint32_t koff = (uint32_t)ks * 32;
            uint32_t ah[4][4], al[4][4], bh[2][4], bl[2][4];
            #pragma unroll
            for (int pr = 0; pr < 2; pr++) {
                uint32_t bb = (uint32_t)(warp_n * 32 + pr * 16) * ROWB + koff + b_lane_off;
                ldsm_x4(bh[pr], stb + SB_HI + bb);
                ldsm_x4(bl[pr], stb + SB_LO + bb);
            }
            #pragma unroll
            for (int mm = 0; mm < 4; mm++) {
                uint32_t ab = (uint32_t)(warp_m * 64 + mm * 16) * ROWB + koff + a_lane_off;
                ldsm_x4(ah[mm], stb + SA_HI + ab);
                ldsm_x4(al[mm], stb + SA_LO + ab);
            }
            // term-outer: hh over all 16 accs, then hl, then lh
            #pragma unroll
            for (int mm = 0; mm < 4; mm++)
                #pragma unroll
                for (int nn = 0; nn < 4; nn++) {
                    const int pr = nn >> 1, sb2 = (nn & 1) * 2;
                    mma16816(acc[mm][nn], ah[mm], bh[pr][sb2], bh[pr][sb2 + 1]);
                }
            #pragma unroll
            for (int mm = 0; mm < 4; mm++)
                #pragma unroll
                for (int nn = 0; nn < 4; nn++) {
                    const int pr = nn >> 1, sb2 = (nn & 1) * 2;
                    mma16816(acc[mm][nn], ah[mm], bl[pr][sb2], bl[pr][sb2 + 1]);
                }
            #pragma unroll
            for (int mm = 0; mm < 4; mm++)
                #pragma unroll
                for (int nn = 0; nn < 4; nn++) {
                    const int pr = nn >> 1, sb2 = (nn & 1) * 2;
                    mma16816(acc[mm][nn], al[mm], bh[pr][sb2], bh[pr][sb2 + 1]);
                }
        }
    }

    const int g = lane >> 2, tq = lane & 3;
    #pragma unroll
    for (int mm = 0; mm < 4; mm++) {
        #pragma unroll
        for (int nn = 0; nn < 4; nn++) {
            int row = row0 + warp_m * 64 + mm * 16 + g;
            int col = col0 + warp_n * 32 + nn * 8 + tq * 2;
            if (Chi) {
                #pragma unroll
                for (int half = 0; half < 2; half++) {
                    float v0 = acc[mm][nn][half * 2 + 0];
                    float v1 = acc[mm][nn][half * 2 + 1];
                    float h0 = bf16_round(v0), h1 = bf16_round(v1);
                    size_t idx = (size_t)(row + half * 8) * Ntot + col;
                    *reinterpret_cast<uint32_t*>(Chi + idx) = pack_bf16x2(h0, h1);
                    *reinterpret_cast<uint32_t*>(Clo + idx) = pack_bf16x2(v0 - h0, v1 - h1);
                }
            } else {
                *reinterpret_cast<float2*>(&Cf[(size_t)row * Ntot + col]) =
                    make_float2(acc[mm][nn][0], acc[mm][nn][1]);
                *reinterpret_cast<float2*>(&Cf[(size_t)(row + 8) * Ntot + col]) =
                    make_float2(acc[mm][nn][2], acc[mm][nn][3]);
            }
        }
    }
}

// ---------------------------------------------------------------------------
// Flash attention via mma.sync, bf16 hi/lo split, cp.async 2-stage KV
// pipeline. Term-outer mma issue in the S-loop; p reuses the sacc registers.
// CTA = 128 q-rows x one (b,h). 8 warps x 16 q-rows. j-blocks of 64.
// ---------------------------------------------------------------------------
#define AROWB 144
#define SQ_HI 0
#define SQ_LO 18432
#define AKV0 36864
#define ASTAGE 36864
#define AK_HI 0
#define AK_LO 9216
#define AV_HI 18432
#define AV_LO 27648
#define ATTN_SMEM (AKV0 + 2 * ASTAGE)

__global__ __launch_bounds__(256) void mma_attn_kernel(
    const __nv_bfloat16* __restrict__ qkvh, const __nv_bfloat16* __restrict__ qkvl,
    __nv_bfloat16* __restrict__ yh, __nv_bfloat16* __restrict__ yl)
{
    extern __shared__ __align__(16) char sm[];
    const uint32_t smb = smem_u32(sm);
    const int tid = threadIdx.x;
    const int w = tid >> 5;
    const int lane = tid & 31;
    const int g = lane >> 2, tq = lane & 3;
    const int qb = blockIdx.x;
    const int bh = blockIdx.y;
    const int b = bh >> 4, h = bh & 15;

    const int kv_r0 = tid >> 3, kv_c = tid & 7;
    const uint32_t kv_dst0 = (uint32_t)kv_r0 * AROWB + (uint32_t)kv_c * 16;
    const uint32_t kv_dst1 = (uint32_t)(kv_r0 + 32) * AROWB + (uint32_t)kv_c * 16;

    auto load_kv = [&](int jb, int st) {
        const int j0 = jb * 64;
        const uint32_t base = smb + AKV0 + (uint32_t)st * ASTAGE;
        size_t k0s = ((size_t)(b * SS + j0 + kv_r0)) * (3 * DD) + DD + h * HD + kv_c * 8;
        size_t k1s = k0s + (size_t)32 * (3 * DD);
        cp_async16(base + AK_HI + kv_dst0, qkvh + k0s);
        cp_async16(base + AK_HI + kv_dst1, qkvh + k1s);
        cp_async16(base + AK_LO + kv_dst0, qkvl + k0s);
        cp_async16(base + AK_LO + kv_dst1, qkvl + k1s);
        cp_async16(base + AV_HI + kv_dst0, qkvh + k0s + DD);
        cp_async16(base + AV_HI + kv_dst1, qkvh + k1s + DD);
        cp_async16(base + AV_LO + kv_dst0, qkvl + k0s + DD);
        cp_async16(base + AV_LO + kv_dst1, qkvl + k1s + DD);
    };

    // Stage Q tiles (group 0), prefetch KV block 0 (group 1)
    #pragma unroll
    for (int i = 0; i < 4; i++) {
        int u = tid + i * 256;
        int r = u >> 3, c = u & 7;
        uint32_t dst = (uint32_t)r * AROWB + (uint32_t)c * 16;
        size_t src = ((size_t)(b * SS + qb * 128 + r)) * (3 * DD) + h * HD + c * 8;
        cp_async16(smb + SQ_HI + dst, qkvh + src);
        cp_async16(smb + SQ_LO + dst, qkvl + src);
    }
    CP_COMMIT();
    load_kv(0, 0);
    CP_COMMIT();

    CP_WAIT(1);          // Q resident
    __syncthreads();

    const uint32_t a_off = (uint32_t)(lane & 15) * AROWB + ((lane >> 4) & 1) * 16;
    uint32_t qfh[4][4], qfl[4][4];
    #pragma unroll
    for (int t = 0; t < 4; t++) {
        uint32_t base = (uint32_t)(w * 16) * AROWB + (uint32_t)t * 32 + a_off;
        ldsm_x4(qfh[t], smb + SQ_HI + base);
        ldsm_x4(qfl[t], smb + SQ_LO + base);
    }

    float yacc[8][4] = {};
    float m0 = -1e30f, m1 = -1e30f, l0 = 0.0f, l1 = 0.0f;

    const uint32_t b_off = ((uint32_t)((lane & 7) + ((lane >> 4) & 1) * 8)) * AROWB
                         + ((lane >> 3) & 1) * 16;
    const uint32_t v_off = (uint32_t)(lane & 15) * AROWB + ((lane >> 4) & 1) * 16;
    const int rowbase = qb * 128 + w * 16;

    const int njb = 2 * qb + 2;
    for (int jb = 0; jb < njb; jb++) {
        const int j0 = jb * 64;
        CP_WAIT(0);
        __syncthreads();
        if (jb + 1 < njb) {
            load_kv(jb + 1, (jb + 1) & 1);
            CP_COMMIT();
        }

        if (j0 <= rowbase + 15) {   // strip not fully above diagonal
            const uint32_t kvb = smb + AKV0 + (uint32_t)(jb & 1) * ASTAGE;

            // S = Q K^T (hi*hi + hi*lo + lo*hi), term-outer per t
            float sacc[8][4] = {};
            #pragma unroll
            for (int t = 0; t < 4; t++) {
                uint32_t kh[4][4], kl[4][4];
                #pragma unroll
                for (int pr = 0; pr < 4; pr++) {
                    uint32_t ad = (uint32_t)(pr * 16) * AROWB + (uint32_t)t * 32 + b_off;
                    ldsm_x4(kh[pr], kvb + AK_HI + ad);
                    ldsm_x4(kl[pr], kvb + AK_LO + ad);
                }
                #pragma unroll
                for (int nn = 0; nn < 8; nn++) {
                    const int pr = nn >> 1, s2 = (nn & 1) * 2;
                    mma16816(sacc[nn], qfh[t], kh[pr][s2], kh[pr][s2 + 1]);
                }
                #pragma unroll
                for (int nn = 0; nn < 8; nn++) {
                    const int pr = nn >> 1, s2 = (nn & 1) * 2;
                    mma16816(sacc[nn], qfh[t], kl[pr][s2], kl[pr][s2 + 1]);
                }
                #pragma unroll
                for (int nn = 0; nn < 8; nn++) {
                    const int pr = nn >> 1, s2 = (nn & 1) * 2;
                    mma16816(sacc[nn], qfl[t], kh[pr][s2], kh[pr][s2 + 1]);
                }
            }

            #pragma unroll
            for (int nn = 0; nn < 8; nn++)
                #pragma unroll
                for (int e = 0; e < 4; e++) sacc[nn][e] *= 0.125f;

            if (j0 + 63 > rowbase) {
                const int r0 = rowbase + g, r1 = r0 + 8;
                #pragma unroll
                for (int nn = 0; nn < 8; nn++) {
                    int col = j0 + nn * 8 + 2 * tq;
                    if (col > r0)     sacc[nn][0] = -1e30f;
                    if (col + 1 > r0) sacc[nn][1] = -1e30f;
                    if (col > r1)     sacc[nn][2] = -1e30f;
                    if (col + 1 > r1) sacc[nn][3] = -1e30f;
                }
            }

            // Online softmax (rows g, g+8)
            float mx0 = -1e30f, mx1 = -1e30f;
            #pragma unroll
            for (int nn = 0; nn < 8; nn++) {
                mx0 = fmaxf(mx0, fmaxf(sacc[nn][0], sacc[nn][1]));
                mx1 = fmaxf(mx1, fmaxf(sacc[nn][2], sacc[nn][3]));
            }
            mx0 = fmaxf(mx0, __shfl_xor_sync(0xffffffffu, mx0, 1));
            mx0 = fmaxf(mx0, __shfl_xor_sync(0xffffffffu, mx0, 2));
            mx1 = fmaxf(mx1, __shfl_xor_sync(0xffffffffu, mx1, 1));
            mx1 = fmaxf(mx1, __shfl_xor_sync(0xffffffffu, mx1, 2));

            float mn0 = fmaxf(m0, mx0), mn1 = fmaxf(m1, mx1);
            float f0 = __expf(m0 - mn0), f1 = __expf(m1 - mn1);
            m0 = mn0; m1 = mn1;

            // p overwrites sacc in place
            float ps0 = 0.0f, ps1 = 0.0f;
            #pragma unroll
            for (int nn = 0; nn < 8; nn++) {
                sacc[nn][0] = __expf(sacc[nn][0] - m0);
                sacc[nn][1] = __expf(sacc[nn][1] - m0);
                sacc[nn][2] = __expf(sacc[nn][2] - m1);
                sacc[nn][3] = __expf(sacc[nn][3] - m1);
                ps0 += sacc[nn][0] + sacc[nn][1];
                ps1 += sacc[nn][2] + sacc[nn][3];
            }
            ps0 += __shfl_xor_sync(0xffffffffu, ps0, 1);
            ps0 += __shfl_xor_sync(0xffffffffu, ps0, 2);
            ps1 += __shfl_xor_sync(0xffffffffu, ps1, 1);
            ps1 += __shfl_xor_sync(0xffffffffu, ps1, 2);
            l0 = l0 * f0 + ps0;
            l1 = l1 * f1 + ps1;

            #pragma unroll
            for (int nn = 0; nn < 8; nn++) {
                yacc[nn][0] *= f0; yacc[nn][1] *= f0;
                yacc[nn][2] *= f1; yacc[nn][3] *= f1;
            }

            // y += P V per k16-step t; mma is non-volatile so ptxas can
            // interleave across the unrolled d16 iterations.
            #pragma unroll
            for (int t = 0; t < 4; t++) {
                uint32_t ph[4], pl[4];
                #pragma unroll
                for (int q2 = 0; q2 < 2; q2++) {
                    const float* pp = sacc[2 * t + q2];
                    float h0 = bf16_round(pp[0]), h1 = bf16_round(pp[1]);
                    float h2 = bf16_round(pp[2]), h3 = bf16_round(pp[3]);
                    ph[2 * q2 + 0] = pack_bf16x2(h0, h1);
                    ph[2 * q2 + 1] = pack_bf16x2(h2, h3);
                    pl[2 * q2 + 0] = pack_bf16x2(pp[0] - h0, pp[1] - h1);
                    pl[2 * q2 + 1] = pack_bf16x2(pp[2] - h2, pp[3] - h3);
                }
                #pragma unroll
                for (int d16 = 0; d16 < 4; d16++) {
                    uint32_t vh[4], vl[4];
                    uint32_t ad = (uint32_t)(16 * t) * AROWB + (uint32_t)d16 * 32 + v_off;
                    ldsm_x4_trans(vh, kvb + AV_HI + ad);
                    ldsm_x4_trans(vl, kvb + AV_LO + ad);
                    mma16816(yacc[2 * d16 + 0], ph, vh[0], vh[1]);
                    mma16816(yacc[2 * d16 + 1], ph, vh[2], vh[3]);
                    mma16816(yacc[2 * d16 + 0], ph, vl[0], vl[1]);
                    mma16816(yacc[2 * d16 + 1], ph, vl[2], vl[3]);
                    mma16816(yacc[2 * d16 + 0], pl, vh[0], vh[1]);
                    mma16816(yacc[2 * d16 + 1], pl, vh[2], vh[3]);
                }
            }
        }
    }

    // Epilogue: y /= l, write bf16 hi/lo
    const float i0 = 1.0f / l0, i1 = 1.0f / l1;
    const int grow0 = b * SS + qb * 128 + w * 16 + g;
    #pragma unroll
    for (int nn = 0; nn < 8; nn++) {
        int col = h * HD + nn * 8 + 2 * tq;
        float v0 = yacc[nn][0] * i0, v1 = yacc[nn][1] * i0;
        float v2 = yacc[nn][2] * i1, v3 = yacc[nn][3] * i1;
        float h0 = bf16_round(v0), h1 = bf16_round(v1);
        float h2 = bf16_round(v2), h3 = bf16_round(v3);
        size_t idx0 = (size_t)grow0 * DD + col;
        size_t idx1 = (size_t)(grow0 + 8) * DD + col;
        *reinterpret_cast<uint32_t*>(yh + idx0) = pack_bf16x2(h0, h1);
        *reinterpret_cast<uint32_t*>(yl + idx0) = pack_bf16x2(v0 - h0, v1 - h1);
        *reinterpret_cast<uint32_t*>(yh + idx1) = pack_bf16x2(h2, h3);
        *reinterpret_cast<uint32_t*>(yl + idx1) = pack_bf16x2(v2 - h2, v3 - h3);
    }
}

// ---------------------------------------------------------------------------
// Launch
// ---------------------------------------------------------------------------
extern "C" void kernel_launch(void* const* d_in, const int* in_sizes, int n_in,
                              void* d_out, int out_size)
{
    const float* x      = (const float*)d_in[0];
    const float* w_qkv  = (const float*)d_in[1];
    const float* w_proj = (const float*)d_in[2];
    float* out = (float*)d_out;

    __nv_bfloat16 *xhi, *xlo, *qkvh, *qkvl, *yh, *yl;
    __nv_bfloat16 *wqT_hi, *wqT_lo, *wpT_hi, *wpT_lo;
    cudaGetSymbolAddress((void**)&xhi, g_xhi);
    cudaGetSymbolAddress((void**)&xlo, g_xlo);
    cudaGetSymbolAddress((void**)&qkvh, g_qkvh);
    cudaGetSymbolAddress((void**)&qkvl, g_qkvl);
    cudaGetSymbolAddress((void**)&yh, g_yh);
    cudaGetSymbolAddress((void**)&yl, g_yl);
    cudaGetSymbolAddress((void**)&wqT_hi, g_wqkvT_hi);
    cudaGetSymbolAddress((void**)&wqT_lo, g_wqkvT_lo);
    cudaGetSymbolAddress((void**)&wpT_hi, g_wprojT_hi);
    cudaGetSymbolAddress((void**)&wpT_lo, g_wprojT_lo);

    cudaFuncSetAttribute(mma_gemm_kernel,
                         cudaFuncAttributeMaxDynamicSharedMemorySize, GEMM_SMEM);
    cudaFuncSetAttribute(mma_attn_kernel,
                         cudaFuncAttributeMaxDynamicSharedMemorySize, ATTN_SMEM);

    const int M = BB * SS;
    const int nElemX = M * DD;

    split_kernel<<<nElemX / 1024, 256>>>(
        (const float4*)x, (uint32_t*)xhi, (uint32_t*)xlo, nElemX / 4);
    transpose_split_kernel<<<dim3(3 * DD / 32, DD / 32), 256>>>(w_qkv, wqT_hi, wqT_lo, DD, 3 * DD);
    transpose_split_kernel<<<dim3(DD / 32, DD / 32), 256>>>(w_proj, wpT_hi, wpT_lo, DD, DD);

    mma_gemm_kernel<<<dim3(3 * DD / 128, M / 128), 256, GEMM_SMEM>>>(
        xhi, xlo, wqT_hi, wqT_lo, nullptr, qkvh, qkvl, 3 * DD, DD);

    mma_attn_kernel<<<dim3(SS / 128, BB * NH), 256, ATTN_SMEM>>>(qkvh, qkvl, yh, yl);

    mma_gemm_kernel<<<dim3(DD / 128, M / 128), 256, GEMM_SMEM>>>(
        yh, yl, wpT_hi, wpT_lo, out, nullptr, nullptr, DD, DD);
}

// round 8
// speedup vs baseline: 2.3077x; 2.3047x over previous
#include <cuda_runtime.h>
#include <cuda_fp16.h>
#include <cstdint>

// Problem constants: B=2, S=2048, D=1024, H=16, HD=64
#define BB 2
#define SS 2048
#define DD 1024
#define NH 16
#define HD 64

// ---------------------------------------------------------------------------
// mma.sync / ldmatrix / cp.async helpers (plain PTX)
// ---------------------------------------------------------------------------
__device__ __forceinline__ uint32_t smem_u32(const void* p) {
    uint32_t a;
    asm("{ .reg .u64 t; cvta.to.shared.u64 t, %1; cvt.u32.u64 %0, t; }"
        : "=r"(a) : "l"(p));
    return a;
}
__device__ __forceinline__ void ldsm_x4(uint32_t* r, uint32_t addr) {
    asm volatile("ldmatrix.sync.aligned.m8n8.x4.shared.b16 {%0,%1,%2,%3}, [%4];"
        : "=r"(r[0]), "=r"(r[1]), "=r"(r[2]), "=r"(r[3]) : "r"(addr));
}
__device__ __forceinline__ void ldsm_x4_trans(uint32_t* r, uint32_t addr) {
    asm volatile("ldmatrix.sync.aligned.m8n8.x4.trans.shared.b16 {%0,%1,%2,%3}, [%4];"
        : "=r"(r[0]), "=r"(r[1]), "=r"(r[2]), "=r"(r[3]) : "r"(addr));
}
// fp16 mma, non-volatile (pure register op)
__device__ __forceinline__ void mma16816(float* c, const uint32_t* a,
                                         uint32_t b0, uint32_t b1) {
    asm("mma.sync.aligned.m16n8k16.row.col.f32.f16.f16.f32 "
        "{%0,%1,%2,%3}, {%4,%5,%6,%7}, {%8,%9}, {%0,%1,%2,%3};"
        : "+f"(c[0]), "+f"(c[1]), "+f"(c[2]), "+f"(c[3])
        : "r"(a[0]), "r"(a[1]), "r"(a[2]), "r"(a[3]), "r"(b0), "r"(b1));
}
__device__ __forceinline__ void cp_async16(uint32_t dst, const void* src) {
    asm volatile("cp.async.cg.shared.global [%0], [%1], 16;"
        :: "r"(dst), "l"(src));
}
#define CP_COMMIT() asm volatile("cp.async.commit_group;" ::: "memory")
#define CP_WAIT(n)  asm volatile("cp.async.wait_group %0;" :: "n"(n) : "memory")

// pack two floats -> f16x2 (first arg = low half)
__device__ __forceinline__ uint32_t pack_f16x2(float lo_elem, float hi_elem) {
    __half2 h = __floats2half2_rn(lo_elem, hi_elem);
    return *reinterpret_cast<uint32_t*>(&h);
}

// ---------------------------------------------------------------------------
// Scratch (__device__ globals; allocation-free rule)
// ---------------------------------------------------------------------------
__device__ __half g_xh[(size_t)BB * SS * DD];
__device__ __half g_qkvh[(size_t)BB * SS * 3 * DD];   // [4096, 3072] fp16
__device__ __half g_yh[(size_t)BB * SS * DD];         // [4096, 1024] fp16
__device__ __half g_wqkvT[(size_t)3 * DD * DD];       // [3072, 1024] K-major fp16
__device__ __half g_wprojT[(size_t)DD * DD];          // [1024, 1024] K-major fp16

// ---------------------------------------------------------------------------
// fp32 -> fp16 convert, vectorized
// ---------------------------------------------------------------------------
__global__ __launch_bounds__(256) void tohalf_kernel(
    const float4* __restrict__ in, uint32_t* __restrict__ out, int n4)
{
    int i = blockIdx.x * 256 + threadIdx.x;
    if (i < n4) {
        float4 v = in[i];
        out[i * 2 + 0] = pack_f16x2(v.x, v.y);
        out[i * 2 + 1] = pack_f16x2(v.z, v.w);
    }
}

// ---------------------------------------------------------------------------
// Transpose + convert: in [K,N] fp32 -> outT [N,K] fp16 (K-major)
// ---------------------------------------------------------------------------
__global__ __launch_bounds__(256) void transpose_tohalf_kernel(
    const float* __restrict__ in, __half* __restrict__ outT, int K, int N)
{
    __shared__ float t[32][33];
    const int tx = threadIdx.x & 31;
    const int ty = threadIdx.x >> 5;
    const int n0 = blockIdx.x * 32;
    const int k0 = blockIdx.y * 32;
    #pragma unroll
    for (int i = 0; i < 4; i++) {
        int k = k0 + ty + i * 8;
        t[ty + i * 8][tx] = in[(size_t)k * N + n0 + tx];
    }
    __syncthreads();
    #pragma unroll
    for (int i = 0; i < 4; i++) {
        int n = n0 + ty + i * 8;
        int k = k0 + tx;
        outT[(size_t)n * K + k] = __float2half_rn(t[tx][ty + i * 8]);
    }
}

// ---------------------------------------------------------------------------
// fp16 GEMM via mma.sync, cp.async 2-stage, one barrier per K-chunk.
// C = A[M,K] @ B[N,K]^T, fp32 accumulate; output fp32 (Cf) or fp16 (Ch).
// CTA 128x128, BK=32, 256 threads (8 warps 2x4), warp tile 64x32.
// Rows padded to 80B (mod-8 x 16B covers all bank groups; conflict-free ldsm).
// ---------------------------------------------------------------------------
#define ROWB 80
#define GSTAGE 20480
#define SA_OF 0
#define SB_OF 10240
#define GEMM_SMEM (2 * GSTAGE)

__global__ __launch_bounds__(256, 2) void mma_gemm_kernel(
    const __half* __restrict__ A, const __half* __restrict__ B,
    float* __restrict__ Cf, __half* __restrict__ Ch, int Ntot, int K)
{
    extern __shared__ __align__(16) char sm[];
    const uint32_t smb = smem_u32(sm);

    const int tid = threadIdx.x;
    const int wid = tid >> 5;
    const int lane = tid & 31;
    const int warp_m = wid >> 2;
    const int warp_n = wid & 3;
    const int row0 = blockIdx.y * 128;
    const int col0 = blockIdx.x * 128;

    const uint32_t a_lane_off = (uint32_t)(lane & 15) * ROWB + ((lane >> 4) & 1) * 16;
    const uint32_t b_lane_off = ((uint32_t)((lane & 7) + ((lane >> 4) & 1) * 8)) * ROWB
                              + ((lane >> 3) & 1) * 16;

    const int l_r0 = tid >> 2, l_c = (tid & 3);
    const uint32_t l_dst0 = (uint32_t)l_r0 * ROWB + (uint32_t)l_c * 16;
    const uint32_t l_dst1 = (uint32_t)(l_r0 + 64) * ROWB + (uint32_t)l_c * 16;

    auto load_stage = [&](int kc, int st) {
        const int k0 = kc << 5;
        const uint32_t base = smb + (uint32_t)st * GSTAGE;
        size_t a0 = (size_t)(row0 + l_r0) * K + k0 + l_c * 8;
        size_t b0 = (size_t)(col0 + l_r0) * K + k0 + l_c * 8;
        cp_async16(base + SA_OF + l_dst0, A + a0);
        cp_async16(base + SA_OF + l_dst1, A + a0 + (size_t)64 * K);
        cp_async16(base + SB_OF + l_dst0, B + b0);
        cp_async16(base + SB_OF + l_dst1, B + b0 + (size_t)64 * K);
    };

    float acc[4][4][4] = {};

    const int nchunks = K >> 5;
    load_stage(0, 0);
    CP_COMMIT();

    for (int kc = 0; kc < nchunks; kc++) {
        CP_WAIT(0);
        __syncthreads();
        if (kc + 1 < nchunks) {
            load_stage(kc + 1, (kc + 1) & 1);
            CP_COMMIT();
        }

        const uint32_t stb = smb + (uint32_t)(kc & 1) * GSTAGE;
        #pragma unroll
        for (int ks = 0; ks < 2; ks++) {
            const uint32_t koff = (uint32_t)ks * 32;
            uint32_t ah[4][4], bh[2][4];
            #pragma unroll
            for (int pr = 0; pr < 2; pr++) {
                uint32_t bb = (uint32_t)(warp_n * 32 + pr * 16) * ROWB + koff + b_lane_off;
                ldsm_x4(bh[pr], stb + SB_OF + bb);
            }
            #pragma unroll
            for (int mm = 0; mm < 4; mm++) {
                uint32_t ab = (uint32_t)(warp_m * 64 + mm * 16) * ROWB + koff + a_lane_off;
                ldsm_x4(ah[mm], stb + SA_OF + ab);
            }
            #pragma unroll
            for (int mm = 0; mm < 4; mm++)
                #pragma unroll
                for (int nn = 0; nn < 4; nn++) {
                    const int pr = nn >> 1, sb2 = (nn & 1) * 2;
                    mma16816(acc[mm][nn], ah[mm], bh[pr][sb2], bh[pr][sb2 + 1]);
                }
        }
    }

    const int g = lane >> 2, tq = lane & 3;
    #pragma unroll
    for (int mm = 0; mm < 4; mm++) {
        #pragma unroll
        for (int nn = 0; nn < 4; nn++) {
            int row = row0 + warp_m * 64 + mm * 16 + g;
            int col = col0 + warp_n * 32 + nn * 8 + tq * 2;
            if (Ch) {
                #pragma unroll
                for (int half_i = 0; half_i < 2; half_i++) {
                    size_t idx = (size_t)(row + half_i * 8) * Ntot + col;
                    *reinterpret_cast<uint32_t*>(Ch + idx) =
                        pack_f16x2(acc[mm][nn][half_i * 2 + 0],
                                   acc[mm][nn][half_i * 2 + 1]);
                }
            } else {
                *reinterpret_cast<float2*>(&Cf[(size_t)row * Ntot + col]) =
                    make_float2(acc[mm][nn][0], acc[mm][nn][1]);
                *reinterpret_cast<float2*>(&Cf[(size_t)(row + 8) * Ntot + col]) =
                    make_float2(acc[mm][nn][2], acc[mm][nn][3]);
            }
        }
    }
}

// ---------------------------------------------------------------------------
// Flash attention via fp16 mma.sync, cp.async 2-stage KV pipeline.
// CTA = 128 q-rows x one (b,h). 8 warps x 16 q-rows. j-blocks of 64.
// Rows padded to 144B (9x16B, gcd(9,8)=1 -> conflict-free ldmatrix).
// Warps fully above the diagonal skip the block's compute.
// ---------------------------------------------------------------------------
#define AROWB 144
#define SQ_OF 0
#define AKV0 18432
#define ASTAGE 18432
#define AK_OF 0
#define AV_OF 9216
#define ATTN_SMEM (AKV0 + 2 * ASTAGE)

__global__ __launch_bounds__(256) void mma_attn_kernel(
    const __half* __restrict__ qkv, __half* __restrict__ y)
{
    extern __shared__ __align__(16) char sm[];
    const uint32_t smb = smem_u32(sm);
    const int tid = threadIdx.x;
    const int w = tid >> 5;
    const int lane = tid & 31;
    const int g = lane >> 2, tq = lane & 3;
    const int qb = blockIdx.x;
    const int bh = blockIdx.y;
    const int b = bh >> 4, h = bh & 15;

    const int kv_r0 = tid >> 3, kv_c = tid & 7;
    const uint32_t kv_dst0 = (uint32_t)kv_r0 * AROWB + (uint32_t)kv_c * 16;
    const uint32_t kv_dst1 = (uint32_t)(kv_r0 + 32) * AROWB + (uint32_t)kv_c * 16;

    auto load_kv = [&](int jb, int st) {
        const int j0 = jb * 64;
        const uint32_t base = smb + AKV0 + (uint32_t)st * ASTAGE;
        size_t k0s = ((size_t)(b * SS + j0 + kv_r0)) * (3 * DD) + DD + h * HD + kv_c * 8;
        size_t k1s = k0s + (size_t)32 * (3 * DD);
        cp_async16(base + AK_OF + kv_dst0, qkv + k0s);
        cp_async16(base + AK_OF + kv_dst1, qkv + k1s);
        cp_async16(base + AV_OF + kv_dst0, qkv + k0s + DD);
        cp_async16(base + AV_OF + kv_dst1, qkv + k1s + DD);
    };

    // Stage Q (group 0), prefetch KV block 0 (group 1)
    #pragma unroll
    for (int i = 0; i < 4; i++) {
        int u = tid + i * 256;
        int r = u >> 3, c = u & 7;
        uint32_t dst = (uint32_t)r * AROWB + (uint32_t)c * 16;
        size_t src = ((size_t)(b * SS + qb * 128 + r)) * (3 * DD) + h * HD + c * 8;
        cp_async16(smb + SQ_OF + dst, qkv + src);
    }
    CP_COMMIT();
    load_kv(0, 0);
    CP_COMMIT();

    CP_WAIT(1);          // Q resident
    __syncthreads();

    const uint32_t a_off = (uint32_t)(lane & 15) * AROWB + ((lane >> 4) & 1) * 16;
    uint32_t qf[4][4];
    #pragma unroll
    for (int t = 0; t < 4; t++) {
        uint32_t base = (uint32_t)(w * 16) * AROWB + (uint32_t)t * 32 + a_off;
        ldsm_x4(qf[t], smb + SQ_OF + base);
    }

    float yacc[8][4] = {};
    float m0 = -1e30f, m1 = -1e30f, l0 = 0.0f, l1 = 0.0f;

    const uint32_t b_off = ((uint32_t)((lane & 7) + ((lane >> 4) & 1) * 8)) * AROWB
                         + ((lane >> 3) & 1) * 16;
    const uint32_t v_off = (uint32_t)(lane & 15) * AROWB + ((lane >> 4) & 1) * 16;
    const int rowbase = qb * 128 + w * 16;

    const int njb = 2 * qb + 2;
    for (int jb = 0; jb < njb; jb++) {
        const int j0 = jb * 64;
        CP_WAIT(0);
        __syncthreads();
        if (jb + 1 < njb) {
            load_kv(jb + 1, (jb + 1) & 1);
            CP_COMMIT();
        }

        if (j0 <= rowbase + 15) {   // strip not fully above diagonal
            const uint32_t kvb = smb + AKV0 + (uint32_t)(jb & 1) * ASTAGE;

            // S = Q K^T
            float sacc[8][4] = {};
            #pragma unroll
            for (int t = 0; t < 4; t++) {
                uint32_t kh[4][4];
                #pragma unroll
                for (int pr = 0; pr < 4; pr++) {
                    uint32_t ad = (uint32_t)(pr * 16) * AROWB + (uint32_t)t * 32 + b_off;
                    ldsm_x4(kh[pr], kvb + AK_OF + ad);
                }
                #pragma unroll
                for (int nn = 0; nn < 8; nn++) {
                    const int pr = nn >> 1, s2 = (nn & 1) * 2;
                    mma16816(sacc[nn], qf[t], kh[pr][s2], kh[pr][s2 + 1]);
                }
            }

            #pragma unroll
            for (int nn = 0; nn < 8; nn++)
                #pragma unroll
                for (int e = 0; e < 4; e++) sacc[nn][e] *= 0.125f;

            if (j0 + 63 > rowbase) {
                const int r0 = rowbase + g, r1 = r0 + 8;
                #pragma unroll
                for (int nn = 0; nn < 8; nn++) {
                    int col = j0 + nn * 8 + 2 * tq;
                    if (col > r0)     sacc[nn][0] = -1e30f;
                    if (col + 1 > r0) sacc[nn][1] = -1e30f;
                    if (col > r1)     sacc[nn][2] = -1e30f;
                    if (col + 1 > r1) sacc[nn][3] = -1e30f;
                }
            }

            // Online softmax (rows g, g+8)
            float mx0 = -1e30f, mx1 = -1e30f;
            #pragma unroll
            for (int nn = 0; nn < 8; nn++) {
                mx0 = fmaxf(mx0, fmaxf(sacc[nn][0], sacc[nn][1]));
                mx1 = fmaxf(mx1, fmaxf(sacc[nn][2], sacc[nn][3]));
            }
            mx0 = fmaxf(mx0, __shfl_xor_sync(0xffffffffu, mx0, 1));
            mx0 = fmaxf(mx0, __shfl_xor_sync(0xffffffffu, mx0, 2));
            mx1 = fmaxf(mx1, __shfl_xor_sync(0xffffffffu, mx1, 1));
            mx1 = fmaxf(mx1, __shfl_xor_sync(0xffffffffu, mx1, 2));

            float mn0 = fmaxf(m0, mx0), mn1 = fmaxf(m1, mx1);
            float f0 = __expf(m0 - mn0), f1 = __expf(m1 - mn1);
            m0 = mn0; m1 = mn1;

            // p overwrites sacc in place
            float ps0 = 0.0f, ps1 = 0.0f;
            #pragma unroll
            for (int nn = 0; nn < 8; nn++) {
                sacc[nn][0] = __expf(sacc[nn][0] - m0);
                sacc[nn][1] = __expf(sacc[nn][1] - m0);
                sacc[nn][2] = __expf(sacc[nn][2] - m1);
                sacc[nn][3] = __expf(sacc[nn][3] - m1);
                ps0 += sacc[nn][0] + sacc[nn][1];
                ps1 += sacc[nn][2] + sacc[nn][3];
            }
            ps0 += __shfl_xor_sync(0xffffffffu, ps0, 1);
            ps0 += __shfl_xor_sync(0xffffffffu, ps0, 2);
            ps1 += __shfl_xor_sync(0xffffffffu, ps1, 1);
            ps1 += __shfl_xor_sync(0xffffffffu, ps1, 2);
            l0 = l0 * f0 + ps0;
            l1 = l1 * f1 + ps1;

            #pragma unroll
            for (int nn = 0; nn < 8; nn++) {
                yacc[nn][0] *= f0; yacc[nn][1] *= f0;
                yacc[nn][2] *= f1; yacc[nn][3] *= f1;
            }

            // y += P V (V via ldmatrix.trans)
            #pragma unroll
            for (int t = 0; t < 4; t++) {
                uint32_t ph[4];
                #pragma unroll
                for (int q2 = 0; q2 < 2; q2++) {
                    const float* pp = sacc[2 * t + q2];
                    ph[2 * q2 + 0] = pack_f16x2(pp[0], pp[1]);
                    ph[2 * q2 + 1] = pack_f16x2(pp[2], pp[3]);
                }
                #pragma unroll
                for (int d16 = 0; d16 < 4; d16++) {
                    uint32_t vh[4];
                    uint32_t ad = (uint32_t)(16 * t) * AROWB + (uint32_t)d16 * 32 + v_off;
                    ldsm_x4_trans(vh, kvb + AV_OF + ad);
                    mma16816(yacc[2 * d16 + 0], ph, vh[0], vh[1]);
                    mma16816(yacc[2 * d16 + 1], ph, vh[2], vh[3]);
                }
            }
        }
    }

    // Epilogue: y /= l, write fp16
    const float i0 = 1.0f / l0, i1 = 1.0f / l1;
    const int grow0 = b * SS + qb * 128 + w * 16 + g;
    #pragma unroll
    for (int nn = 0; nn < 8; nn++) {
        int col = h * HD + nn * 8 + 2 * tq;
        size_t idx0 = (size_t)grow0 * DD + col;
        size_t idx1 = (size_t)(grow0 + 8) * DD + col;
        *reinterpret_cast<uint32_t*>(y + idx0) =
            pack_f16x2(yacc[nn][0] * i0, yacc[nn][1] * i0);
        *reinterpret_cast<uint32_t*>(y + idx1) =
            pack_f16x2(yacc[nn][2] * i1, yacc[nn][3] * i1);
    }
}

// ---------------------------------------------------------------------------
// Launch
// ---------------------------------------------------------------------------
extern "C" void kernel_launch(void* const* d_in, const int* in_sizes, int n_in,
                              void* d_out, int out_size)
{
    const float* x      = (const float*)d_in[0];
    const float* w_qkv  = (const float*)d_in[1];
    const float* w_proj = (const float*)d_in[2];
    float* out = (float*)d_out;

    __half *xh, *qkvh, *yh, *wqT, *wpT;
    cudaGetSymbolAddress((void**)&xh, g_xh);
    cudaGetSymbolAddress((void**)&qkvh, g_qkvh);
    cudaGetSymbolAddress((void**)&yh, g_yh);
    cudaGetSymbolAddress((void**)&wqT, g_wqkvT);
    cudaGetSymbolAddress((void**)&wpT, g_wprojT);

    cudaFuncSetAttribute(mma_gemm_kernel,
                         cudaFuncAttributeMaxDynamicSharedMemorySize, GEMM_SMEM);
    cudaFuncSetAttribute(mma_attn_kernel,
                         cudaFuncAttributeMaxDynamicSharedMemorySize, ATTN_SMEM);

    const int M = BB * SS;
    const int nElemX = M * DD;

    tohalf_kernel<<<nElemX / 1024, 256>>>(
        (const float4*)x, (uint32_t*)xh, nElemX / 4);
    transpose_tohalf_kernel<<<dim3(3 * DD / 32, DD / 32), 256>>>(w_qkv, wqT, DD, 3 * DD);
    transpose_tohalf_kernel<<<dim3(DD / 32, DD / 32), 256>>>(w_proj, wpT, DD, DD);

    // qkv = x @ w_qkv -> fp16
    mma_gemm_kernel<<<dim3(3 * DD / 128, M / 128), 256, GEMM_SMEM>>>(
        xh, wqT, nullptr, qkvh, 3 * DD, DD);

    // attention -> y fp16
    mma_attn_kernel<<<dim3(SS / 128, BB * NH), 256, ATTN_SMEM>>>(qkvh, yh);

    // out = y @ w_proj -> fp32
    mma_gemm_kernel<<<dim3(DD / 128, M / 128), 256, GEMM_SMEM>>>(
        yh, wpT, out, nullptr, DD, DD);
}

// round 9
// speedup vs baseline: 2.4119x; 1.0452x over previous
#include <cuda_runtime.h>
#include <cuda_fp16.h>
#include <cstdint>

// Problem constants: B=2, S=2048, D=1024, H=16, HD=64
#define BB 2
#define SS 2048
#define DD 1024
#define NH 16
#define HD 64

// ---------------------------------------------------------------------------
// mma.sync / ldmatrix / cp.async helpers (plain PTX)
// ---------------------------------------------------------------------------
__device__ __forceinline__ uint32_t smem_u32(const void* p) {
    uint32_t a;
    asm("{ .reg .u64 t; cvta.to.shared.u64 t, %1; cvt.u32.u64 %0, t; }"
        : "=r"(a) : "l"(p));
    return a;
}
__device__ __forceinline__ void ldsm_x4(uint32_t* r, uint32_t addr) {
    asm volatile("ldmatrix.sync.aligned.m8n8.x4.shared.b16 {%0,%1,%2,%3}, [%4];"
        : "=r"(r[0]), "=r"(r[1]), "=r"(r[2]), "=r"(r[3]) : "r"(addr));
}
__device__ __forceinline__ void ldsm_x4_trans(uint32_t* r, uint32_t addr) {
    asm volatile("ldmatrix.sync.aligned.m8n8.x4.trans.shared.b16 {%0,%1,%2,%3}, [%4];"
        : "=r"(r[0]), "=r"(r[1]), "=r"(r[2]), "=r"(r[3]) : "r"(addr));
}
// fp16 mma, non-volatile (pure register op)
__device__ __forceinline__ void mma16816(float* c, const uint32_t* a,
                                         uint32_t b0, uint32_t b1) {
    asm("mma.sync.aligned.m16n8k16.row.col.f32.f16.f16.f32 "
        "{%0,%1,%2,%3}, {%4,%5,%6,%7}, {%8,%9}, {%0,%1,%2,%3};"
        : "+f"(c[0]), "+f"(c[1]), "+f"(c[2]), "+f"(c[3])
        : "r"(a[0]), "r"(a[1]), "r"(a[2]), "r"(a[3]), "r"(b0), "r"(b1));
}
__device__ __forceinline__ void cp_async16(uint32_t dst, const void* src) {
    asm volatile("cp.async.cg.shared.global [%0], [%1], 16;"
        :: "r"(dst), "l"(src));
}
#define CP_COMMIT() asm volatile("cp.async.commit_group;" ::: "memory")
#define CP_WAIT(n)  asm volatile("cp.async.wait_group %0;" :: "n"(n) : "memory")

// pack two floats -> f16x2 (first arg = low half)
__device__ __forceinline__ uint32_t pack_f16x2(float lo_elem, float hi_elem) {
    __half2 h = __floats2half2_rn(lo_elem, hi_elem);
    return *reinterpret_cast<uint32_t*>(&h);
}

// ---------------------------------------------------------------------------
// Scratch (__device__ globals; allocation-free rule)
// ---------------------------------------------------------------------------
__device__ __half g_xh[(size_t)BB * SS * DD];
__device__ __half g_qkvh[(size_t)BB * SS * 3 * DD];   // [4096, 3072] fp16
__device__ __half g_yh[(size_t)BB * SS * DD];         // [4096, 1024] fp16
__device__ __half g_wqkvT[(size_t)3 * DD * DD];       // [3072, 1024] K-major fp16
__device__ __half g_wprojT[(size_t)DD * DD];          // [1024, 1024] K-major fp16

// ---------------------------------------------------------------------------
// fp32 -> fp16 convert, vectorized
// ---------------------------------------------------------------------------
__global__ __launch_bounds__(256) void tohalf_kernel(
    const float4* __restrict__ in, uint32_t* __restrict__ out, int n4)
{
    int i = blockIdx.x * 256 + threadIdx.x;
    if (i < n4) {
        float4 v = in[i];
        out[i * 2 + 0] = pack_f16x2(v.x, v.y);
        out[i * 2 + 1] = pack_f16x2(v.z, v.w);
    }
}

// ---------------------------------------------------------------------------
// Transpose + convert: in [K,N] fp32 -> outT [N,K] fp16 (K-major)
// ---------------------------------------------------------------------------
__global__ __launch_bounds__(256) void transpose_tohalf_kernel(
    const float* __restrict__ in, __half* __restrict__ outT, int K, int N)
{
    __shared__ float t[32][33];
    const int tx = threadIdx.x & 31;
    const int ty = threadIdx.x >> 5;
    const int n0 = blockIdx.x * 32;
    const int k0 = blockIdx.y * 32;
    #pragma unroll
    for (int i = 0; i < 4; i++) {
        int k = k0 + ty + i * 8;
        t[ty + i * 8][tx] = in[(size_t)k * N + n0 + tx];
    }
    __syncthreads();
    #pragma unroll
    for (int i = 0; i < 4; i++) {
        int n = n0 + ty + i * 8;
        int k = k0 + tx;
        outT[(size_t)n * K + k] = __float2half_rn(t[tx][ty + i * 8]);
    }
}

// ---------------------------------------------------------------------------
// fp16 GEMM via mma.sync, cp.async 2-stage, BK=64, warp tile 64x64.
// C = A[M,K] @ B[N,K]^T, fp32 accumulate; output fp32 (Cf) or fp16 (Ch).
// CTA 128x128, 128 threads (4 warps, 2x2 grid of 64x64 warp tiles).
// Per k16-step: 8 ldsm.x4 feed 32 mmas; one barrier per 4 k16-steps.
// Rows padded to 144B (9x16B, gcd(9,8)=1 -> conflict-free ldmatrix).
// Per-accumulator k16 order unchanged (0..K/16-1) -> bit-identical numerics.
// ---------------------------------------------------------------------------
#define ROWB 144
#define SA_OF 0
#define SB_OF 18432
#define GSTAGE 36864
#define GEMM_SMEM (2 * GSTAGE)

__global__ __launch_bounds__(128, 2) void mma_gemm_kernel(
    const __half* __restrict__ A, const __half* __restrict__ B,
    float* __restrict__ Cf, __half* __restrict__ Ch, int Ntot, int K)
{
    extern __shared__ __align__(16) char sm[];
    const uint32_t smb = smem_u32(sm);

    const int tid = threadIdx.x;
    const int wid = tid >> 5;
    const int lane = tid & 31;
    const int warp_m = wid >> 1;          // 0..1 -> rows warp_m*64
    const int warp_n = wid & 1;           // 0..1 -> cols warp_n*64
    const int row0 = blockIdx.y * 128;
    const int col0 = blockIdx.x * 128;

    const uint32_t a_lane_off = (uint32_t)(lane & 15) * ROWB + ((lane >> 4) & 1) * 16;
    const uint32_t b_lane_off = ((uint32_t)((lane & 7) + ((lane >> 4) & 1) * 8)) * ROWB
                              + ((lane >> 3) & 1) * 16;

    // load coords: 16 rows x 8 cols per pass, 8 passes -> 128x64 halfs
    const int l_r0 = tid >> 3, l_c = tid & 7;

    auto load_stage = [&](int kc, int st) {
        const int k0 = kc << 6;           // BK = 64 halfs
        const uint32_t base = smb + (uint32_t)st * GSTAGE;
        #pragma unroll
        for (int i = 0; i < 8; i++) {
            int r = l_r0 + i * 16;
            uint32_t dst = (uint32_t)r * ROWB + (uint32_t)l_c * 16;
            cp_async16(base + SA_OF + dst, A + (size_t)(row0 + r) * K + k0 + l_c * 8);
            cp_async16(base + SB_OF + dst, B + (size_t)(col0 + r) * K + k0 + l_c * 8);
        }
    };

    float acc[4][8][4] = {};

    const int nchunks = K >> 6;
    load_stage(0, 0);
    CP_COMMIT();

    for (int kc = 0; kc < nchunks; kc++) {
        CP_WAIT(0);
        __syncthreads();
        if (kc + 1 < nchunks) {
            load_stage(kc + 1, (kc + 1) & 1);
            CP_COMMIT();
        }

        const uint32_t stb = smb + (uint32_t)(kc & 1) * GSTAGE;
        #pragma unroll
        for (int t = 0; t < 4; t++) {
            const uint32_t koff = (uint32_t)t * 32;
            uint32_t ah[4][4], bh[4][4];
            #pragma unroll
            for (int pr = 0; pr < 4; pr++) {
                uint32_t bb = (uint32_t)(warp_n * 64 + pr * 16) * ROWB + koff + b_lane_off;
                ldsm_x4(bh[pr], stb + SB_OF + bb);
            }
            #pragma unroll
            for (int mm = 0; mm < 4; mm++) {
                uint32_t ab = (uint32_t)(warp_m * 64 + mm * 16) * ROWB + koff + a_lane_off;
                ldsm_x4(ah[mm], stb + SA_OF + ab);
            }
            #pragma unroll
            for (int mm = 0; mm < 4; mm++)
                #pragma unroll
                for (int nn = 0; nn < 8; nn++) {
                    const int pr = nn >> 1, s2 = (nn & 1) * 2;
                    mma16816(acc[mm][nn], ah[mm], bh[pr][s2], bh[pr][s2 + 1]);
                }
        }
    }

    const int g = lane >> 2, tq = lane & 3;
    #pragma unroll
    for (int mm = 0; mm < 4; mm++) {
        #pragma unroll
        for (int nn = 0; nn < 8; nn++) {
            int row = row0 + warp_m * 64 + mm * 16 + g;
            int col = col0 + warp_n * 64 + nn * 8 + tq * 2;
            if (Ch) {
                #pragma unroll
                for (int half_i = 0; half_i < 2; half_i++) {
                    size_t idx = (size_t)(row + half_i * 8) * Ntot + col;
                    *reinterpret_cast<uint32_t*>(Ch + idx) =
                        pack_f16x2(acc[mm][nn][half_i * 2 + 0],
                                   acc[mm][nn][half_i * 2 + 1]);
                }
            } else {
                *reinterpret_cast<float2*>(&Cf[(size_t)row * Ntot + col]) =
                    make_float2(acc[mm][nn][0], acc[mm][nn][1]);
                *reinterpret_cast<float2*>(&Cf[(size_t)(row + 8) * Ntot + col]) =
                    make_float2(acc[mm][nn][2], acc[mm][nn][3]);
            }
        }
    }
}

// ---------------------------------------------------------------------------
// Flash attention via fp16 mma.sync, cp.async 2-stage KV pipeline.
// CTA = 128 q-rows x one (b,h). 8 warps x 16 q-rows. j-blocks of 64.
// (unchanged from R8)
// ---------------------------------------------------------------------------
#define AROWB 144
#define SQ_OF 0
#define AKV0 18432
#define ASTAGE 18432
#define AK_OF 0
#define AV_OF 9216
#define ATTN_SMEM (AKV0 + 2 * ASTAGE)

__global__ __launch_bounds__(256) void mma_attn_kernel(
    const __half* __restrict__ qkv, __half* __restrict__ y)
{
    extern __shared__ __align__(16) char sm[];
    const uint32_t smb = smem_u32(sm);
    const int tid = threadIdx.x;
    const int w = tid >> 5;
    const int lane = tid & 31;
    const int g = lane >> 2, tq = lane & 3;
    const int qb = blockIdx.x;
    const int bh = blockIdx.y;
    const int b = bh >> 4, h = bh & 15;

    const int kv_r0 = tid >> 3, kv_c = tid & 7;
    const uint32_t kv_dst0 = (uint32_t)kv_r0 * AROWB + (uint32_t)kv_c * 16;
    const uint32_t kv_dst1 = (uint32_t)(kv_r0 + 32) * AROWB + (uint32_t)kv_c * 16;

    auto load_kv = [&](int jb, int st) {
        const int j0 = jb * 64;
        const uint32_t base = smb + AKV0 + (uint32_t)st * ASTAGE;
        size_t k0s = ((size_t)(b * SS + j0 + kv_r0)) * (3 * DD) + DD + h * HD + kv_c * 8;
        size_t k1s = k0s + (size_t)32 * (3 * DD);
        cp_async16(base + AK_OF + kv_dst0, qkv + k0s);
        cp_async16(base + AK_OF + kv_dst1, qkv + k1s);
        cp_async16(base + AV_OF + kv_dst0, qkv + k0s + DD);
        cp_async16(base + AV_OF + kv_dst1, qkv + k1s + DD);
    };

    // Stage Q (group 0), prefetch KV block 0 (group 1)
    #pragma unroll
    for (int i = 0; i < 4; i++) {
        int u = tid + i * 256;
        int r = u >> 3, c = u & 7;
        uint32_t dst = (uint32_t)r * AROWB + (uint32_t)c * 16;
        size_t src = ((size_t)(b * SS + qb * 128 + r)) * (3 * DD) + h * HD + c * 8;
        cp_async16(smb + SQ_OF + dst, qkv + src);
    }
    CP_COMMIT();
    load_kv(0, 0);
    CP_COMMIT();

    CP_WAIT(1);          // Q resident
    __syncthreads();

    const uint32_t a_off = (uint32_t)(lane & 15) * AROWB + ((lane >> 4) & 1) * 16;
    uint32_t qf[4][4];
    #pragma unroll
    for (int t = 0; t < 4; t++) {
        uint32_t base = (uint32_t)(w * 16) * AROWB + (uint32_t)t * 32 + a_off;
        ldsm_x4(qf[t], smb + SQ_OF + base);
    }

    float yacc[8][4] = {};
    float m0 = -1e30f, m1 = -1e30f, l0 = 0.0f, l1 = 0.0f;

    const uint32_t b_off = ((uint32_t)((lane & 7) + ((lane >> 4) & 1) * 8)) * AROWB
                         + ((lane >> 3) & 1) * 16;
    const uint32_t v_off = (uint32_t)(lane & 15) * AROWB + ((lane >> 4) & 1) * 16;
    const int rowbase = qb * 128 + w * 16;

    const int njb = 2 * qb + 2;
    for (int jb = 0; jb < njb; jb++) {
        const int j0 = jb * 64;
        CP_WAIT(0);
        __syncthreads();
        if (jb + 1 < njb) {
            load_kv(jb + 1, (jb + 1) & 1);
            CP_COMMIT();
        }

        if (j0 <= rowbase + 15) {   // strip not fully above diagonal
            const uint32_t kvb = smb + AKV0 + (uint32_t)(jb & 1) * ASTAGE;

            // S = Q K^T
            float sacc[8][4] = {};
            #pragma unroll
            for (int t = 0; t < 4; t++) {
                uint32_t kh[4][4];
                #pragma unroll
                for (int pr = 0; pr < 4; pr++) {
                    uint32_t ad = (uint32_t)(pr * 16) * AROWB + (uint32_t)t * 32 + b_off;
                    ldsm_x4(kh[pr], kvb + AK_OF + ad);
                }
                #pragma unroll
                for (int nn = 0; nn < 8; nn++) {
                    const int pr = nn >> 1, s2 = (nn & 1) * 2;
                    mma16816(sacc[nn], qf[t], kh[pr][s2], kh[pr][s2 + 1]);
                }
            }

            #pragma unroll
            for (int nn = 0; nn < 8; nn++)
                #pragma unroll
                for (int e = 0; e < 4; e++) sacc[nn][e] *= 0.125f;

            if (j0 + 63 > rowbase) {
                const int r0 = rowbase + g, r1 = r0 + 8;
                #pragma unroll
                for (int nn = 0; nn < 8; nn++) {
                    int col = j0 + nn * 8 + 2 * tq;
                    if (col > r0)     sacc[nn][0] = -1e30f;
                    if (col + 1 > r0) sacc[nn][1] = -1e30f;
                    if (col > r1)     sacc[nn][2] = -1e30f;
                    if (col + 1 > r1) sacc[nn][3] = -1e30f;
                }
            }

            // Online softmax (rows g, g+8)
            float mx0 = -1e30f, mx1 = -1e30f;
            #pragma unroll
            for (int nn = 0; nn < 8; nn++) {
                mx0 = fmaxf(mx0, fmaxf(sacc[nn][0], sacc[nn][1]));
                mx1 = fmaxf(mx1, fmaxf(sacc[nn][2], sacc[nn][3]));
            }
            mx0 = fmaxf(mx0, __shfl_xor_sync(0xffffffffu, mx0, 1));
            mx0 = fmaxf(mx0, __shfl_xor_sync(0xffffffffu, mx0, 2));
            mx1 = fmaxf(mx1, __shfl_xor_sync(0xffffffffu, mx1, 1));
            mx1 = fmaxf(mx1, __shfl_xor_sync(0xffffffffu, mx1, 2));

            float mn0 = fmaxf(m0, mx0), mn1 = fmaxf(m1, mx1);
            float f0 = __expf(m0 - mn0), f1 = __expf(m1 - mn1);
            m0 = mn0; m1 = mn1;

            // p overwrites sacc in place
            float ps0 = 0.0f, ps1 = 0.0f;
            #pragma unroll
            for (int nn = 0; nn < 8; nn++) {
                sacc[nn][0] = __expf(sacc[nn][0] - m0);
                sacc[nn][1] = __expf(sacc[nn][1] - m0);
                sacc[nn][2] = __expf(sacc[nn][2] - m1);
                sacc[nn][3] = __expf(sacc[nn][3] - m1);
                ps0 += sacc[nn][0] + sacc[nn][1];
                ps1 += sacc[nn][2] + sacc[nn][3];
            }
            ps0 += __shfl_xor_sync(0xffffffffu, ps0, 1);
            ps0 += __shfl_xor_sync(0xffffffffu, ps0, 2);
            ps1 += __shfl_xor_sync(0xffffffffu, ps1, 1);
            ps1 += __shfl_xor_sync(0xffffffffu, ps1, 2);
            l0 = l0 * f0 + ps0;
            l1 = l1 * f1 + ps1;

            #pragma unroll
            for (int nn = 0; nn < 8; nn++) {
                yacc[nn][0] *= f0; yacc[nn][1] *= f0;
                yacc[nn][2] *= f1; yacc[nn][3] *= f1;
            }

            // y += P V (V via ldmatrix.trans)
            #pragma unroll
            for (int t = 0; t < 4; t++) {
                uint32_t ph[4];
                #pragma unroll
                for (int q2 = 0; q2 < 2; q2++) {
                    const float* pp = sacc[2 * t + q2];
                    ph[2 * q2 + 0] = pack_f16x2(pp[0], pp[1]);
                    ph[2 * q2 + 1] = pack_f16x2(pp[2], pp[3]);
                }
                #pragma unroll
                for (int d16 = 0; d16 < 4; d16++) {
                    uint32_t vh[4];
                    uint32_t ad = (uint32_t)(16 * t) * AROWB + (uint32_t)d16 * 32 + v_off;
                    ldsm_x4_trans(vh, kvb + AV_OF + ad);
                    mma16816(yacc[2 * d16 + 0], ph, vh[0], vh[1]);
                    mma16816(yacc[2 * d16 + 1], ph, vh[2], vh[3]);
                }
            }
        }
    }

    // Epilogue: y /= l, write fp16
    const float i0 = 1.0f / l0, i1 = 1.0f / l1;
    const int grow0 = b * SS + qb * 128 + w * 16 + g;
    #pragma unroll
    for (int nn = 0; nn < 8; nn++) {
        int col = h * HD + nn * 8 + 2 * tq;
        size_t idx0 = (size_t)grow0 * DD + col;
        size_t idx1 = (size_t)(grow0 + 8) * DD + col;
        *reinterpret_cast<uint32_t*>(y + idx0) =
            pack_f16x2(yacc[nn][0] * i0, yacc[nn][1] * i0);
        *reinterpret_cast<uint32_t*>(y + idx1) =
            pack_f16x2(yacc[nn][2] * i1, yacc[nn][3] * i1);
    }
}

// ---------------------------------------------------------------------------
// Launch
// ---------------------------------------------------------------------------
extern "C" void kernel_launch(void* const* d_in, const int* in_sizes, int n_in,
                              void* d_out, int out_size)
{
    const float* x      = (const float*)d_in[0];
    const float* w_qkv  = (const float*)d_in[1];
    const float* w_proj = (const float*)d_in[2];
    float* out = (float*)d_out;

    __half *xh, *qkvh, *yh, *wqT, *wpT;
    cudaGetSymbolAddress((void**)&xh, g_xh);
    cudaGetSymbolAddress((void**)&qkvh, g_qkvh);
    cudaGetSymbolAddress((void**)&yh, g_yh);
    cudaGetSymbolAddress((void**)&wqT, g_wqkvT);
    cudaGetSymbolAddress((void**)&wpT, g_wprojT);

    cudaFuncSetAttribute(mma_gemm_kernel,
                         cudaFuncAttributeMaxDynamicSharedMemorySize, GEMM_SMEM);
    cudaFuncSetAttribute(mma_attn_kernel,
                         cudaFuncAttributeMaxDynamicSharedMemorySize, ATTN_SMEM);

    const int M = BB * SS;
    const int nElemX = M * DD;

    tohalf_kernel<<<nElemX / 1024, 256>>>(
        (const float4*)x, (uint32_t*)xh, nElemX / 4);
    transpose_tohalf_kernel<<<dim3(3 * DD / 32, DD / 32), 256>>>(w_qkv, wqT, DD, 3 * DD);
    transpose_tohalf_kernel<<<dim3(DD / 32, DD / 32), 256>>>(w_proj, wpT, DD, DD);

    // qkv = x @ w_qkv -> fp16
    mma_gemm_kernel<<<dim3(3 * DD / 128, M / 128), 128, GEMM_SMEM>>>(
        xh, wqT, nullptr, qkvh, 3 * DD, DD);

    // attention -> y fp16
    mma_attn_kernel<<<dim3(SS / 128, BB * NH), 256, ATTN_SMEM>>>(qkvh, yh);

    // out = y @ w_proj -> fp32
    mma_gemm_kernel<<<dim3(DD / 128, M / 128), 128, GEMM_SMEM>>>(
        yh, wpT, out, nullptr, DD, DD);
}

// round 10
// speedup vs baseline: 2.4278x; 1.0066x over previous
#include <cuda_runtime.h>
#include <cuda_fp16.h>
#include <cstdint>

// Problem constants: B=2, S=2048, D=1024, H=16, HD=64
#define BB 2
#define SS 2048
#define DD 1024
#define NH 16
#define HD 64

// ---------------------------------------------------------------------------
// mma.sync / ldmatrix / cp.async helpers (plain PTX)
// ---------------------------------------------------------------------------
__device__ __forceinline__ uint32_t smem_u32(const void* p) {
    uint32_t a;
    asm("{ .reg .u64 t; cvta.to.shared.u64 t, %1; cvt.u32.u64 %0, t; }"
        : "=r"(a) : "l"(p));
    return a;
}
__device__ __forceinline__ void ldsm_x4(uint32_t* r, uint32_t addr) {
    asm volatile("ldmatrix.sync.aligned.m8n8.x4.shared.b16 {%0,%1,%2,%3}, [%4];"
        : "=r"(r[0]), "=r"(r[1]), "=r"(r[2]), "=r"(r[3]) : "r"(addr));
}
__device__ __forceinline__ void ldsm_x4_trans(uint32_t* r, uint32_t addr) {
    asm volatile("ldmatrix.sync.aligned.m8n8.x4.trans.shared.b16 {%0,%1,%2,%3}, [%4];"
        : "=r"(r[0]), "=r"(r[1]), "=r"(r[2]), "=r"(r[3]) : "r"(addr));
}
// fp16 mma, non-volatile (pure register op)
__device__ __forceinline__ void mma16816(float* c, const uint32_t* a,
                                         uint32_t b0, uint32_t b1) {
    asm("mma.sync.aligned.m16n8k16.row.col.f32.f16.f16.f32 "
        "{%0,%1,%2,%3}, {%4,%5,%6,%7}, {%8,%9}, {%0,%1,%2,%3};"
        : "+f"(c[0]), "+f"(c[1]), "+f"(c[2]), "+f"(c[3])
        : "r"(a[0]), "r"(a[1]), "r"(a[2]), "r"(a[3]), "r"(b0), "r"(b1));
}
__device__ __forceinline__ void cp_async16(uint32_t dst, const void* src) {
    asm volatile("cp.async.cg.shared.global [%0], [%1], 16;"
        :: "r"(dst), "l"(src));
}
#define CP_COMMIT() asm volatile("cp.async.commit_group;" ::: "memory")
#define CP_WAIT(n)  asm volatile("cp.async.wait_group %0;" :: "n"(n) : "memory")

// pack two floats -> f16x2 (first arg = low half)
__device__ __forceinline__ uint32_t pack_f16x2(float lo_elem, float hi_elem) {
    __half2 h = __floats2half2_rn(lo_elem, hi_elem);
    return *reinterpret_cast<uint32_t*>(&h);
}

// ---------------------------------------------------------------------------
// Scratch (__device__ globals; allocation-free rule)
// ---------------------------------------------------------------------------
__device__ __half g_xh[(size_t)BB * SS * DD];
__device__ __half g_qkvh[(size_t)BB * SS * 3 * DD];   // [4096, 3072] fp16
__device__ __half g_yh[(size_t)BB * SS * DD];         // [4096, 1024] fp16
__device__ __half g_wqkvT[(size_t)3 * DD * DD];       // [3072, 1024] K-major fp16
__device__ __half g_wprojT[(size_t)DD * DD];          // [1024, 1024] K-major fp16

// ---------------------------------------------------------------------------
// fp32 -> fp16 convert, vectorized
// ---------------------------------------------------------------------------
__global__ __launch_bounds__(256) void tohalf_kernel(
    const float4* __restrict__ in, uint32_t* __restrict__ out, int n4)
{
    int i = blockIdx.x * 256 + threadIdx.x;
    if (i < n4) {
        float4 v = in[i];
        out[i * 2 + 0] = pack_f16x2(v.x, v.y);
        out[i * 2 + 1] = pack_f16x2(v.z, v.w);
    }
}

// ---------------------------------------------------------------------------
// Transpose + convert: in [K,N] fp32 -> outT [N,K] fp16 (K-major)
// ---------------------------------------------------------------------------
__global__ __launch_bounds__(256) void transpose_tohalf_kernel(
    const float* __restrict__ in, __half* __restrict__ outT, int K, int N)
{
    __shared__ float t[32][33];
    const int tx = threadIdx.x & 31;
    const int ty = threadIdx.x >> 5;
    const int n0 = blockIdx.x * 32;
    const int k0 = blockIdx.y * 32;
    #pragma unroll
    for (int i = 0; i < 4; i++) {
        int k = k0 + ty + i * 8;
        t[ty + i * 8][tx] = in[(size_t)k * N + n0 + tx];
    }
    __syncthreads();
    #pragma unroll
    for (int i = 0; i < 4; i++) {
        int n = n0 + ty + i * 8;
        int k = k0 + tx;
        outT[(size_t)n * K + k] = __float2half_rn(t[tx][ty + i * 8]);
    }
}

// ---------------------------------------------------------------------------
// fp16 GEMM via mma.sync, cp.async 2-stage, BK=64, warp tile 64x64.
// (unchanged from R9 — within ~10% of the mma-issue floor)
// ---------------------------------------------------------------------------
#define ROWB 144
#define SA_OF 0
#define SB_OF 18432
#define GSTAGE 36864
#define GEMM_SMEM (2 * GSTAGE)

__global__ __launch_bounds__(128, 2) void mma_gemm_kernel(
    const __half* __restrict__ A, const __half* __restrict__ B,
    float* __restrict__ Cf, __half* __restrict__ Ch, int Ntot, int K)
{
    extern __shared__ __align__(16) char sm[];
    const uint32_t smb = smem_u32(sm);

    const int tid = threadIdx.x;
    const int wid = tid >> 5;
    const int lane = tid & 31;
    const int warp_m = wid >> 1;
    const int warp_n = wid & 1;
    const int row0 = blockIdx.y * 128;
    const int col0 = blockIdx.x * 128;

    const uint32_t a_lane_off = (uint32_t)(lane & 15) * ROWB + ((lane >> 4) & 1) * 16;
    const uint32_t b_lane_off = ((uint32_t)((lane & 7) + ((lane >> 4) & 1) * 8)) * ROWB
                              + ((lane >> 3) & 1) * 16;

    const int l_r0 = tid >> 3, l_c = tid & 7;

    auto load_stage = [&](int kc, int st) {
        const int k0 = kc << 6;
        const uint32_t base = smb + (uint32_t)st * GSTAGE;
        #pragma unroll
        for (int i = 0; i < 8; i++) {
            int r = l_r0 + i * 16;
            uint32_t dst = (uint32_t)r * ROWB + (uint32_t)l_c * 16;
            cp_async16(base + SA_OF + dst, A + (size_t)(row0 + r) * K + k0 + l_c * 8);
            cp_async16(base + SB_OF + dst, B + (size_t)(col0 + r) * K + k0 + l_c * 8);
        }
    };

    float acc[4][8][4] = {};

    const int nchunks = K >> 6;
    load_stage(0, 0);
    CP_COMMIT();

    for (int kc = 0; kc < nchunks; kc++) {
        CP_WAIT(0);
        __syncthreads();
        if (kc + 1 < nchunks) {
            load_stage(kc + 1, (kc + 1) & 1);
            CP_COMMIT();
        }

        const uint32_t stb = smb + (uint32_t)(kc & 1) * GSTAGE;
        #pragma unroll
        for (int t = 0; t < 4; t++) {
            const uint32_t koff = (uint32_t)t * 32;
            uint32_t ah[4][4], bh[4][4];
            #pragma unroll
            for (int pr = 0; pr < 4; pr++) {
                uint32_t bb = (uint32_t)(warp_n * 64 + pr * 16) * ROWB + koff + b_lane_off;
                ldsm_x4(bh[pr], stb + SB_OF + bb);
            }
            #pragma unroll
            for (int mm = 0; mm < 4; mm++) {
                uint32_t ab = (uint32_t)(warp_m * 64 + mm * 16) * ROWB + koff + a_lane_off;
                ldsm_x4(ah[mm], stb + SA_OF + ab);
            }
            #pragma unroll
            for (int mm = 0; mm < 4; mm++)
                #pragma unroll
                for (int nn = 0; nn < 8; nn++) {
                    const int pr = nn >> 1, s2 = (nn & 1) * 2;
                    mma16816(acc[mm][nn], ah[mm], bh[pr][s2], bh[pr][s2 + 1]);
                }
        }
    }

    const int g = lane >> 2, tq = lane & 3;
    #pragma unroll
    for (int mm = 0; mm < 4; mm++) {
        #pragma unroll
        for (int nn = 0; nn < 8; nn++) {
            int row = row0 + warp_m * 64 + mm * 16 + g;
            int col = col0 + warp_n * 64 + nn * 8 + tq * 2;
            if (Ch) {
                #pragma unroll
                for (int half_i = 0; half_i < 2; half_i++) {
                    size_t idx = (size_t)(row + half_i * 8) * Ntot + col;
                    *reinterpret_cast<uint32_t*>(Ch + idx) =
                        pack_f16x2(acc[mm][nn][half_i * 2 + 0],
                                   acc[mm][nn][half_i * 2 + 1]);
                }
            } else {
                *reinterpret_cast<float2*>(&Cf[(size_t)row * Ntot + col]) =
                    make_float2(acc[mm][nn][0], acc[mm][nn][1]);
                *reinterpret_cast<float2*>(&Cf[(size_t)(row + 8) * Ntot + col]) =
                    make_float2(acc[mm][nn][2], acc[mm][nn][3]);
            }
        }
    }
}

// ---------------------------------------------------------------------------
// Flash attention via fp16 mma.sync, cp.async 2-stage KV pipeline.
// CTA = 128 q-rows x one (b,h); NOW 4 warps x 32 q-rows (2 m-tiles per warp):
// K/V fragments are loaded once per warp and reused across both m-tiles,
// halving ldsm traffic per mma (ratio 2.0 -> 3.2) and barrier participants.
// Per-row accumulation order identical to R9 -> bit-identical output.
// ---------------------------------------------------------------------------
#define AROWB 144
#define SQ_OF 0
#define AKV0 18432
#define ASTAGE 18432
#define AK_OF 0
#define AV_OF 9216
#define ATTN_SMEM (AKV0 + 2 * ASTAGE)

__global__ __launch_bounds__(128, 2) void mma_attn_kernel(
    const __half* __restrict__ qkv, __half* __restrict__ y)
{
    extern __shared__ __align__(16) char sm[];
    const uint32_t smb = smem_u32(sm);
    const int tid = threadIdx.x;
    const int w = tid >> 5;              // 0..3
    const int lane = tid & 31;
    const int g = lane >> 2, tq = lane & 3;
    const int qb = blockIdx.x;
    const int bh = blockIdx.y;
    const int b = bh >> 4, h = bh & 15;

    // KV loader: 128 threads, 64 rows x 8 uint4 per tile -> 4 rows-passes
    const int kv_r0 = tid >> 3, kv_c = tid & 7;   // rows 0..15, col 0..7

    auto load_kv = [&](int jb, int st) {
        const int j0 = jb * 64;
        const uint32_t base = smb + AKV0 + (uint32_t)st * ASTAGE;
        #pragma unroll
        for (int p = 0; p < 4; p++) {
            int r = kv_r0 + p * 16;
            uint32_t dst = (uint32_t)r * AROWB + (uint32_t)kv_c * 16;
            size_t ks = ((size_t)(b * SS + j0 + r)) * (3 * DD) + DD + h * HD + kv_c * 8;
            cp_async16(base + AK_OF + dst, qkv + ks);
            cp_async16(base + AV_OF + dst, qkv + ks + DD);
        }
    };

    // Stage Q (group 0): 128 rows x 8 uint4, 8 per thread
    #pragma unroll
    for (int i = 0; i < 8; i++) {
        int u = tid + i * 128;
        int r = u >> 3, c = u & 7;
        uint32_t dst = (uint32_t)r * AROWB + (uint32_t)c * 16;
        size_t src = ((size_t)(b * SS + qb * 128 + r)) * (3 * DD) + h * HD + c * 8;
        cp_async16(smb + SQ_OF + dst, qkv + src);
    }
    CP_COMMIT();
    load_kv(0, 0);
    CP_COMMIT();

    CP_WAIT(1);          // Q resident
    __syncthreads();

    const uint32_t a_off = (uint32_t)(lane & 15) * AROWB + ((lane >> 4) & 1) * 16;
    uint32_t qf[2][4][4];
    #pragma unroll
    for (int mm = 0; mm < 2; mm++)
        #pragma unroll
        for (int t = 0; t < 4; t++) {
            uint32_t base = (uint32_t)(w * 32 + mm * 16) * AROWB + (uint32_t)t * 32 + a_off;
            ldsm_x4(qf[mm][t], smb + SQ_OF + base);
        }

    float yacc[2][8][4] = {};
    float m0[2] = {-1e30f, -1e30f}, m1[2] = {-1e30f, -1e30f};
    float l0[2] = {0.0f, 0.0f},     l1[2] = {0.0f, 0.0f};

    const uint32_t b_off = ((uint32_t)((lane & 7) + ((lane >> 4) & 1) * 8)) * AROWB
                         + ((lane >> 3) & 1) * 16;
    const uint32_t v_off = (uint32_t)(lane & 15) * AROWB + ((lane >> 4) & 1) * 16;
    const int rowbase = qb * 128 + w * 32;

    const int njb = 2 * qb + 2;
    for (int jb = 0; jb < njb; jb++) {
        const int j0 = jb * 64;
        CP_WAIT(0);
        __syncthreads();
        if (jb + 1 < njb) {
            load_kv(jb + 1, (jb + 1) & 1);
            CP_COMMIT();
        }

        if (j0 <= rowbase + 31) {   // strip (32 rows) not fully above diagonal
            const uint32_t kvb = smb + AKV0 + (uint32_t)(jb & 1) * ASTAGE;

            // S = Q K^T for both m-tiles; K fragments loaded once per t
            float sacc[2][8][4] = {};
            #pragma unroll
            for (int t = 0; t < 4; t++) {
                uint32_t kh[4][4];
                #pragma unroll
                for (int pr = 0; pr < 4; pr++) {
                    uint32_t ad = (uint32_t)(pr * 16) * AROWB + (uint32_t)t * 32 + b_off;
                    ldsm_x4(kh[pr], kvb + AK_OF + ad);
                }
                #pragma unroll
                for (int mm = 0; mm < 2; mm++)
                    #pragma unroll
                    for (int nn = 0; nn < 8; nn++) {
                        const int pr = nn >> 1, s2 = (nn & 1) * 2;
                        mma16816(sacc[mm][nn], qf[mm][t], kh[pr][s2], kh[pr][s2 + 1]);
                    }
            }

            #pragma unroll
            for (int mm = 0; mm < 2; mm++) {
                #pragma unroll
                for (int nn = 0; nn < 8; nn++)
                    #pragma unroll
                    for (int e = 0; e < 4; e++) sacc[mm][nn][e] *= 0.125f;

                const int mrow = rowbase + mm * 16;
                if (j0 + 63 > mrow) {
                    const int r0 = mrow + g, r1 = r0 + 8;
                    #pragma unroll
                    for (int nn = 0; nn < 8; nn++) {
                        int col = j0 + nn * 8 + 2 * tq;
                        if (col > r0)     sacc[mm][nn][0] = -1e30f;
                        if (col + 1 > r0) sacc[mm][nn][1] = -1e30f;
                        if (col > r1)     sacc[mm][nn][2] = -1e30f;
                        if (col + 1 > r1) sacc[mm][nn][3] = -1e30f;
                    }
                }

                // Online softmax (rows g, g+8 of this m-tile)
                float mx0 = -1e30f, mx1 = -1e30f;
                #pragma unroll
                for (int nn = 0; nn < 8; nn++) {
                    mx0 = fmaxf(mx0, fmaxf(sacc[mm][nn][0], sacc[mm][nn][1]));
                    mx1 = fmaxf(mx1, fmaxf(sacc[mm][nn][2], sacc[mm][nn][3]));
                }
                mx0 = fmaxf(mx0, __shfl_xor_sync(0xffffffffu, mx0, 1));
                mx0 = fmaxf(mx0, __shfl_xor_sync(0xffffffffu, mx0, 2));
                mx1 = fmaxf(mx1, __shfl_xor_sync(0xffffffffu, mx1, 1));
                mx1 = fmaxf(mx1, __shfl_xor_sync(0xffffffffu, mx1, 2));

                float mn0 = fmaxf(m0[mm], mx0), mn1 = fmaxf(m1[mm], mx1);
                float f0 = __expf(m0[mm] - mn0), f1 = __expf(m1[mm] - mn1);
                m0[mm] = mn0; m1[mm] = mn1;

                float ps0 = 0.0f, ps1 = 0.0f;
                #pragma unroll
                for (int nn = 0; nn < 8; nn++) {
                    sacc[mm][nn][0] = __expf(sacc[mm][nn][0] - mn0);
                    sacc[mm][nn][1] = __expf(sacc[mm][nn][1] - mn0);
                    sacc[mm][nn][2] = __expf(sacc[mm][nn][2] - mn1);
                    sacc[mm][nn][3] = __expf(sacc[mm][nn][3] - mn1);
                    ps0 += sacc[mm][nn][0] + sacc[mm][nn][1];
                    ps1 += sacc[mm][nn][2] + sacc[mm][nn][3];
                }
                ps0 += __shfl_xor_sync(0xffffffffu, ps0, 1);
                ps0 += __shfl_xor_sync(0xffffffffu, ps0, 2);
                ps1 += __shfl_xor_sync(0xffffffffu, ps1, 1);
                ps1 += __shfl_xor_sync(0xffffffffu, ps1, 2);
                l0[mm] = l0[mm] * f0 + ps0;
                l1[mm] = l1[mm] * f1 + ps1;

                #pragma unroll
                for (int nn = 0; nn < 8; nn++) {
                    yacc[mm][nn][0] *= f0; yacc[mm][nn][1] *= f0;
                    yacc[mm][nn][2] *= f1; yacc[mm][nn][3] *= f1;
                }
            }

            // y += P V : V fragments loaded once per (t, d16), reused for both mm
            #pragma unroll
            for (int t = 0; t < 4; t++) {
                uint32_t ph[2][4];
                #pragma unroll
                for (int mm = 0; mm < 2; mm++)
                    #pragma unroll
                    for (int q2 = 0; q2 < 2; q2++) {
                        const float* pp = sacc[mm][2 * t + q2];
                        ph[mm][2 * q2 + 0] = pack_f16x2(pp[0], pp[1]);
                        ph[mm][2 * q2 + 1] = pack_f16x2(pp[2], pp[3]);
                    }
                #pragma unroll
                for (int d16 = 0; d16 < 4; d16++) {
                    uint32_t vh[4];
                    uint32_t ad = (uint32_t)(16 * t) * AROWB + (uint32_t)d16 * 32 + v_off;
                    ldsm_x4_trans(vh, kvb + AV_OF + ad);
                    #pragma unroll
                    for (int mm = 0; mm < 2; mm++) {
                        mma16816(yacc[mm][2 * d16 + 0], ph[mm], vh[0], vh[1]);
                        mma16816(yacc[mm][2 * d16 + 1], ph[mm], vh[2], vh[3]);
                    }
                }
            }
        }
    }

    // Epilogue: y /= l, write fp16
    #pragma unroll
    for (int mm = 0; mm < 2; mm++) {
        const float i0 = 1.0f / l0[mm], i1 = 1.0f / l1[mm];
        const int grow0 = b * SS + qb * 128 + w * 32 + mm * 16 + g;
        #pragma unroll
        for (int nn = 0; nn < 8; nn++) {
            int col = h * HD + nn * 8 + 2 * tq;
            size_t idx0 = (size_t)grow0 * DD + col;
            size_t idx1 = (size_t)(grow0 + 8) * DD + col;
            *reinterpret_cast<uint32_t*>(y + idx0) =
                pack_f16x2(yacc[mm][nn][0] * i0, yacc[mm][nn][1] * i0);
            *reinterpret_cast<uint32_t*>(y + idx1) =
                pack_f16x2(yacc[mm][nn][2] * i1, yacc[mm][nn][3] * i1);
        }
    }
}

// ---------------------------------------------------------------------------
// Launch
// ---------------------------------------------------------------------------
extern "C" void kernel_launch(void* const* d_in, const int* in_sizes, int n_in,
                              void* d_out, int out_size)
{
    const float* x      = (const float*)d_in[0];
    const float* w_qkv  = (const float*)d_in[1];
    const float* w_proj = (const float*)d_in[2];
    float* out = (float*)d_out;

    __half *xh, *qkvh, *yh, *wqT, *wpT;
    cudaGetSymbolAddress((void**)&xh, g_xh);
    cudaGetSymbolAddress((void**)&qkvh, g_qkvh);
    cudaGetSymbolAddress((void**)&yh, g_yh);
    cudaGetSymbolAddress((void**)&wqT, g_wqkvT);
    cudaGetSymbolAddress((void**)&wpT, g_wprojT);

    cudaFuncSetAttribute(mma_gemm_kernel,
                         cudaFuncAttributeMaxDynamicSharedMemorySize, GEMM_SMEM);
    cudaFuncSetAttribute(mma_attn_kernel,
                         cudaFuncAttributeMaxDynamicSharedMemorySize, ATTN_SMEM);

    const int M = BB * SS;
    const int nElemX = M * DD;

    tohalf_kernel<<<nElemX / 1024, 256>>>(
        (const float4*)x, (uint32_t*)xh, nElemX / 4);
    transpose_tohalf_kernel<<<dim3(3 * DD / 32, DD / 32), 256>>>(w_qkv, wqT, DD, 3 * DD);
    transpose_tohalf_kernel<<<dim3(DD / 32, DD / 32), 256>>>(w_proj, wpT, DD, DD);

    // qkv = x @ w_qkv -> fp16
    mma_gemm_kernel<<<dim3(3 * DD / 128, M / 128), 128, GEMM_SMEM>>>(
        xh, wqT, nullptr, qkvh, 3 * DD, DD);

    // attention -> y fp16
    mma_attn_kernel<<<dim3(SS / 128, BB * NH), 128, ATTN_SMEM>>>(qkvh, yh);

    // out = y @ w_proj -> fp32
    mma_gemm_kernel<<<dim3(DD / 128, M / 128), 128, GEMM_SMEM>>>(
        yh, wpT, out, nullptr, DD, DD);
}

// round 11
// speedup vs baseline: 2.5442x; 1.0479x over previous
#include <cuda_runtime.h>
#include <cuda_fp16.h>
#include <cstdint>

// Problem constants: B=2, S=2048, D=1024, H=16, HD=64
#define BB 2
#define SS 2048
#define DD 1024
#define NH 16
#define HD 64

// ---------------------------------------------------------------------------
// mma.sync / ldmatrix / cp.async helpers (plain PTX)
// ---------------------------------------------------------------------------
__device__ __forceinline__ uint32_t smem_u32(const void* p) {
    uint32_t a;
    asm("{ .reg .u64 t; cvta.to.shared.u64 t, %1; cvt.u32.u64 %0, t; }"
        : "=r"(a) : "l"(p));
    return a;
}
__device__ __forceinline__ void ldsm_x4(uint32_t* r, uint32_t addr) {
    asm volatile("ldmatrix.sync.aligned.m8n8.x4.shared.b16 {%0,%1,%2,%3}, [%4];"
        : "=r"(r[0]), "=r"(r[1]), "=r"(r[2]), "=r"(r[3]) : "r"(addr));
}
__device__ __forceinline__ void ldsm_x4_trans(uint32_t* r, uint32_t addr) {
    asm volatile("ldmatrix.sync.aligned.m8n8.x4.trans.shared.b16 {%0,%1,%2,%3}, [%4];"
        : "=r"(r[0]), "=r"(r[1]), "=r"(r[2]), "=r"(r[3]) : "r"(addr));
}
// fp16 mma, non-volatile (pure register op)
__device__ __forceinline__ void mma16816(float* c, const uint32_t* a,
                                         uint32_t b0, uint32_t b1) {
    asm("mma.sync.aligned.m16n8k16.row.col.f32.f16.f16.f32 "
        "{%0,%1,%2,%3}, {%4,%5,%6,%7}, {%8,%9}, {%0,%1,%2,%3};"
        : "+f"(c[0]), "+f"(c[1]), "+f"(c[2]), "+f"(c[3])
        : "r"(a[0]), "r"(a[1]), "r"(a[2]), "r"(a[3]), "r"(b0), "r"(b1));
}
__device__ __forceinline__ void cp_async16(uint32_t dst, const void* src) {
    asm volatile("cp.async.cg.shared.global [%0], [%1], 16;"
        :: "r"(dst), "l"(src));
}
#define CP_COMMIT() asm volatile("cp.async.commit_group;" ::: "memory")
#define CP_WAIT(n)  asm volatile("cp.async.wait_group %0;" :: "n"(n) : "memory")

// pack two floats -> f16x2 (first arg = low half)
__device__ __forceinline__ uint32_t pack_f16x2(float lo_elem, float hi_elem) {
    __half2 h = __floats2half2_rn(lo_elem, hi_elem);
    return *reinterpret_cast<uint32_t*>(&h);
}

// ---------------------------------------------------------------------------
// Scratch (__device__ globals; allocation-free rule)
// ---------------------------------------------------------------------------
__device__ __half g_xh[(size_t)BB * SS * DD];
__device__ __half g_qkvh[(size_t)BB * SS * 3 * DD];   // [4096, 3072] fp16
__device__ __half g_yh[(size_t)BB * SS * DD];         // [4096, 1024] fp16
__device__ __half g_wqkvT[(size_t)3 * DD * DD];       // [3072, 1024] K-major fp16
__device__ __half g_wprojT[(size_t)DD * DD];          // [1024, 1024] K-major fp16

// ---------------------------------------------------------------------------
// Merged conversion kernel (one launch):
//  role 0: x fp32 -> fp16, 4096 blocks of 1024 elems
//  role 1: w_qkv [K,N] -> wqkvT [N,K], 32x32 tiles, 3*DD/32 x DD/32 = 3072 blks
//          Q columns (n < DD) pre-scaled by 0.125 (folded softmax scale)
//  role 2: w_proj -> wprojT, 1024 blocks
// ---------------------------------------------------------------------------
__global__ __launch_bounds__(256) void convert_kernel(
    const float* __restrict__ x, const float* __restrict__ w_qkv,
    const float* __restrict__ w_proj, __half* __restrict__ xh,
    __half* __restrict__ wqT, __half* __restrict__ wpT)
{
    const int bid = blockIdx.x;
    if (bid < 4096) {
        // tohalf for x
        int i = bid * 256 + threadIdx.x;   // float4 index
        float4 v = reinterpret_cast<const float4*>(x)[i];
        uint32_t* out = reinterpret_cast<uint32_t*>(xh);
        out[i * 2 + 0] = pack_f16x2(v.x, v.y);
        out[i * 2 + 1] = pack_f16x2(v.z, v.w);
        return;
    }
    // transpose roles
    __shared__ float t[32][33];
    const float* in;
    __half* outT;
    int K, N, tb;
    bool scale_q = false;
    if (bid < 4096 + 3072) {
        tb = bid - 4096; in = w_qkv; outT = wqT; K = DD; N = 3 * DD;
        scale_q = true;
    } else {
        tb = bid - (4096 + 3072); in = w_proj; outT = wpT; K = DD; N = DD;
    }
    const int nbx = N / 32;
    const int bx = tb % nbx, by = tb / nbx;
    const int tx = threadIdx.x & 31;
    const int ty = threadIdx.x >> 5;
    const int n0 = bx * 32;
    const int k0 = by * 32;
    #pragma unroll
    for (int i = 0; i < 4; i++) {
        int k = k0 + ty + i * 8;
        t[ty + i * 8][tx] = in[(size_t)k * N + n0 + tx];
    }
    __syncthreads();
    #pragma unroll
    for (int i = 0; i < 4; i++) {
        int n = n0 + ty + i * 8;
        int k = k0 + tx;
        float v = t[tx][ty + i * 8];
        if (scale_q && n < DD) v *= 0.125f;   // fold attention scale into Q
        outT[(size_t)n * K + k] = __float2half_rn(v);
    }
}

// ---------------------------------------------------------------------------
// fp16 GEMM via mma.sync, cp.async 2-stage, BK=64, warp tile 64x64.
// (unchanged from R9 — within ~10% of the mma-issue floor)
// ---------------------------------------------------------------------------
#define ROWB 144
#define SA_OF 0
#define SB_OF 18432
#define GSTAGE 36864
#define GEMM_SMEM (2 * GSTAGE)

__global__ __launch_bounds__(128, 2) void mma_gemm_kernel(
    const __half* __restrict__ A, const __half* __restrict__ B,
    float* __restrict__ Cf, __half* __restrict__ Ch, int Ntot, int K)
{
    extern __shared__ __align__(16) char sm[];
    const uint32_t smb = smem_u32(sm);

    const int tid = threadIdx.x;
    const int wid = tid >> 5;
    const int lane = tid & 31;
    const int warp_m = wid >> 1;
    const int warp_n = wid & 1;
    const int row0 = blockIdx.y * 128;
    const int col0 = blockIdx.x * 128;

    const uint32_t a_lane_off = (uint32_t)(lane & 15) * ROWB + ((lane >> 4) & 1) * 16;
    const uint32_t b_lane_off = ((uint32_t)((lane & 7) + ((lane >> 4) & 1) * 8)) * ROWB
                              + ((lane >> 3) & 1) * 16;

    const int l_r0 = tid >> 3, l_c = tid & 7;

    auto load_stage = [&](int kc, int st) {
        const int k0 = kc << 6;
        const uint32_t base = smb + (uint32_t)st * GSTAGE;
        #pragma unroll
        for (int i = 0; i < 8; i++) {
            int r = l_r0 + i * 16;
            uint32_t dst = (uint32_t)r * ROWB + (uint32_t)l_c * 16;
            cp_async16(base + SA_OF + dst, A + (size_t)(row0 + r) * K + k0 + l_c * 8);
            cp_async16(base + SB_OF + dst, B + (size_t)(col0 + r) * K + k0 + l_c * 8);
        }
    };

    float acc[4][8][4] = {};

    const int nchunks = K >> 6;
    load_stage(0, 0);
    CP_COMMIT();

    for (int kc = 0; kc < nchunks; kc++) {
        CP_WAIT(0);
        __syncthreads();
        if (kc + 1 < nchunks) {
            load_stage(kc + 1, (kc + 1) & 1);
            CP_COMMIT();
        }

        const uint32_t stb = smb + (uint32_t)(kc & 1) * GSTAGE;
        #pragma unroll
        for (int t = 0; t < 4; t++) {
            const uint32_t koff = (uint32_t)t * 32;
            uint32_t ah[4][4], bh[4][4];
            #pragma unroll
            for (int pr = 0; pr < 4; pr++) {
                uint32_t bb = (uint32_t)(warp_n * 64 + pr * 16) * ROWB + koff + b_lane_off;
                ldsm_x4(bh[pr], stb + SB_OF + bb);
            }
            #pragma unroll
            for (int mm = 0; mm < 4; mm++) {
                uint32_t ab = (uint32_t)(warp_m * 64 + mm * 16) * ROWB + koff + a_lane_off;
                ldsm_x4(ah[mm], stb + SA_OF + ab);
            }
            #pragma unroll
            for (int mm = 0; mm < 4; mm++)
                #pragma unroll
                for (int nn = 0; nn < 8; nn++) {
                    const int pr = nn >> 1, s2 = (nn & 1) * 2;
                    mma16816(acc[mm][nn], ah[mm], bh[pr][s2], bh[pr][s2 + 1]);
                }
        }
    }

    const int g = lane >> 2, tq = lane & 3;
    #pragma unroll
    for (int mm = 0; mm < 4; mm++) {
        #pragma unroll
        for (int nn = 0; nn < 8; nn++) {
            int row = row0 + warp_m * 64 + mm * 16 + g;
            int col = col0 + warp_n * 64 + nn * 8 + tq * 2;
            if (Ch) {
                #pragma unroll
                for (int half_i = 0; half_i < 2; half_i++) {
                    size_t idx = (size_t)(row + half_i * 8) * Ntot + col;
                    *reinterpret_cast<uint32_t*>(Ch + idx) =
                        pack_f16x2(acc[mm][nn][half_i * 2 + 0],
                                   acc[mm][nn][half_i * 2 + 1]);
                }
            } else {
                *reinterpret_cast<float2*>(&Cf[(size_t)row * Ntot + col]) =
                    make_float2(acc[mm][nn][0], acc[mm][nn][1]);
                *reinterpret_cast<float2*>(&Cf[(size_t)(row + 8) * Ntot + col]) =
                    make_float2(acc[mm][nn][2], acc[mm][nn][3]);
            }
        }
    }
}

// ---------------------------------------------------------------------------
// Flash attention via fp16 mma.sync, cp.async 2-stage KV pipeline.
// CTA = 128 q-rows x one (b,h); 4 warps x 32 q-rows (2 m-tiles per warp).
// R11: qb REVERSED (heavy CTAs scheduled first -> LPT-style balance);
//      Q pre-scaled by 0.125 in the weights, scale loop removed.
// ---------------------------------------------------------------------------
#define AROWB 144
#define SQ_OF 0
#define AKV0 18432
#define ASTAGE 18432
#define AK_OF 0
#define AV_OF 9216
#define ATTN_SMEM (AKV0 + 2 * ASTAGE)

__global__ __launch_bounds__(128, 2) void mma_attn_kernel(
    const __half* __restrict__ qkv, __half* __restrict__ y)
{
    extern __shared__ __align__(16) char sm[];
    const uint32_t smb = smem_u32(sm);
    const int tid = threadIdx.x;
    const int w = tid >> 5;              // 0..3
    const int lane = tid & 31;
    const int g = lane >> 2, tq = lane & 3;
    const int qb = (int)gridDim.x - 1 - (int)blockIdx.x;   // heavy first
    const int bh = blockIdx.y;
    const int b = bh >> 4, h = bh & 15;

    const int kv_r0 = tid >> 3, kv_c = tid & 7;

    auto load_kv = [&](int jb, int st) {
        const int j0 = jb * 64;
        const uint32_t base = smb + AKV0 + (uint32_t)st * ASTAGE;
        #pragma unroll
        for (int p = 0; p < 4; p++) {
            int r = kv_r0 + p * 16;
            uint32_t dst = (uint32_t)r * AROWB + (uint32_t)kv_c * 16;
            size_t ks = ((size_t)(b * SS + j0 + r)) * (3 * DD) + DD + h * HD + kv_c * 8;
            cp_async16(base + AK_OF + dst, qkv + ks);
            cp_async16(base + AV_OF + dst, qkv + ks + DD);
        }
    };

    // Stage Q (group 0): 128 rows x 8 uint4, 8 per thread
    #pragma unroll
    for (int i = 0; i < 8; i++) {
        int u = tid + i * 128;
        int r = u >> 3, c = u & 7;
        uint32_t dst = (uint32_t)r * AROWB + (uint32_t)c * 16;
        size_t src = ((size_t)(b * SS + qb * 128 + r)) * (3 * DD) + h * HD + c * 8;
        cp_async16(smb + SQ_OF + dst, qkv + src);
    }
    CP_COMMIT();
    load_kv(0, 0);
    CP_COMMIT();

    CP_WAIT(1);          // Q resident
    __syncthreads();

    const uint32_t a_off = (uint32_t)(lane & 15) * AROWB + ((lane >> 4) & 1) * 16;
    uint32_t qf[2][4][4];
    #pragma unroll
    for (int mm = 0; mm < 2; mm++)
        #pragma unroll
        for (int t = 0; t < 4; t++) {
            uint32_t base = (uint32_t)(w * 32 + mm * 16) * AROWB + (uint32_t)t * 32 + a_off;
            ldsm_x4(qf[mm][t], smb + SQ_OF + base);
        }

    float yacc[2][8][4] = {};
    float m0[2] = {-1e30f, -1e30f}, m1[2] = {-1e30f, -1e30f};
    float l0[2] = {0.0f, 0.0f},     l1[2] = {0.0f, 0.0f};

    const uint32_t b_off = ((uint32_t)((lane & 7) + ((lane >> 4) & 1) * 8)) * AROWB
                         + ((lane >> 3) & 1) * 16;
    const uint32_t v_off = (uint32_t)(lane & 15) * AROWB + ((lane >> 4) & 1) * 16;
    const int rowbase = qb * 128 + w * 32;

    const int njb = 2 * qb + 2;
    for (int jb = 0; jb < njb; jb++) {
        const int j0 = jb * 64;
        CP_WAIT(0);
        __syncthreads();
        if (jb + 1 < njb) {
            load_kv(jb + 1, (jb + 1) & 1);
            CP_COMMIT();
        }

        if (j0 <= rowbase + 31) {   // strip (32 rows) not fully above diagonal
            const uint32_t kvb = smb + AKV0 + (uint32_t)(jb & 1) * ASTAGE;

            // S = Q K^T for both m-tiles; K fragments loaded once per t
            float sacc[2][8][4] = {};
            #pragma unroll
            for (int t = 0; t < 4; t++) {
                uint32_t kh[4][4];
                #pragma unroll
                for (int pr = 0; pr < 4; pr++) {
                    uint32_t ad = (uint32_t)(pr * 16) * AROWB + (uint32_t)t * 32 + b_off;
                    ldsm_x4(kh[pr], kvb + AK_OF + ad);
                }
                #pragma unroll
                for (int mm = 0; mm < 2; mm++)
                    #pragma unroll
                    for (int nn = 0; nn < 8; nn++) {
                        const int pr = nn >> 1, s2 = (nn & 1) * 2;
                        mma16816(sacc[mm][nn], qf[mm][t], kh[pr][s2], kh[pr][s2 + 1]);
                    }
            }

            // (scale folded into Q weights; no *0.125 loop)
            #pragma unroll
            for (int mm = 0; mm < 2; mm++) {
                const int mrow = rowbase + mm * 16;
                if (j0 + 63 > mrow) {
                    const int r0 = mrow + g, r1 = r0 + 8;
                    #pragma unroll
                    for (int nn = 0; nn < 8; nn++) {
                        int col = j0 + nn * 8 + 2 * tq;
                        if (col > r0)     sacc[mm][nn][0] = -1e30f;
                        if (col + 1 > r0) sacc[mm][nn][1] = -1e30f;
                        if (col > r1)     sacc[mm][nn][2] = -1e30f;
                        if (col + 1 > r1) sacc[mm][nn][3] = -1e30f;
                    }
                }

                // Online softmax (rows g, g+8 of this m-tile)
                float mx0 = -1e30f, mx1 = -1e30f;
                #pragma unroll
                for (int nn = 0; nn < 8; nn++) {
                    mx0 = fmaxf(mx0, fmaxf(sacc[mm][nn][0], sacc[mm][nn][1]));
                    mx1 = fmaxf(mx1, fmaxf(sacc[mm][nn][2], sacc[mm][nn][3]));
                }
                mx0 = fmaxf(mx0, __shfl_xor_sync(0xffffffffu, mx0, 1));
                mx0 = fmaxf(mx0, __shfl_xor_sync(0xffffffffu, mx0, 2));
                mx1 = fmaxf(mx1, __shfl_xor_sync(0xffffffffu, mx1, 1));
                mx1 = fmaxf(mx1, __shfl_xor_sync(0xffffffffu, mx1, 2));

                float mn0 = fmaxf(m0[mm], mx0), mn1 = fmaxf(m1[mm], mx1);
                float f0 = __expf(m0[mm] - mn0), f1 = __expf(m1[mm] - mn1);
                m0[mm] = mn0; m1[mm] = mn1;

                float ps0 = 0.0f, ps1 = 0.0f;
                #pragma unroll
                for (int nn = 0; nn < 8; nn++) {
                    sacc[mm][nn][0] = __expf(sacc[mm][nn][0] - mn0);
                    sacc[mm][nn][1] = __expf(sacc[mm][nn][1] - mn0);
                    sacc[mm][nn][2] = __expf(sacc[mm][nn][2] - mn1);
                    sacc[mm][nn][3] = __expf(sacc[mm][nn][3] - mn1);
                    ps0 += sacc[mm][nn][0] + sacc[mm][nn][1];
                    ps1 += sacc[mm][nn][2] + sacc[mm][nn][3];
                }
                ps0 += __shfl_xor_sync(0xffffffffu, ps0, 1);
                ps0 += __shfl_xor_sync(0xffffffffu, ps0, 2);
                ps1 += __shfl_xor_sync(0xffffffffu, ps1, 1);
                ps1 += __shfl_xor_sync(0xffffffffu, ps1, 2);
                l0[mm] = l0[mm] * f0 + ps0;
                l1[mm] = l1[mm] * f1 + ps1;

                #pragma unroll
                for (int nn = 0; nn < 8; nn++) {
                    yacc[mm][nn][0] *= f0; yacc[mm][nn][1] *= f0;
                    yacc[mm][nn][2] *= f1; yacc[mm][nn][3] *= f1;
                }
            }

            // y += P V : V fragments loaded once per (t, d16), reused for both mm
            #pragma unroll
            for (int t = 0; t < 4; t++) {
                uint32_t ph[2][4];
                #pragma unroll
                for (int mm = 0; mm < 2; mm++)
                    #pragma unroll
                    for (int q2 = 0; q2 < 2; q2++) {
                        const float* pp = sacc[mm][2 * t + q2];
                        ph[mm][2 * q2 + 0] = pack_f16x2(pp[0], pp[1]);
                        ph[mm][2 * q2 + 1] = pack_f16x2(pp[2], pp[3]);
                    }
                #pragma unroll
                for (int d16 = 0; d16 < 4; d16++) {
                    uint32_t vh[4];
                    uint32_t ad = (uint32_t)(16 * t) * AROWB + (uint32_t)d16 * 32 + v_off;
                    ldsm_x4_trans(vh, kvb + AV_OF + ad);
                    #pragma unroll
                    for (int mm = 0; mm < 2; mm++) {
                        mma16816(yacc[mm][2 * d16 + 0], ph[mm], vh[0], vh[1]);
                        mma16816(yacc[mm][2 * d16 + 1], ph[mm], vh[2], vh[3]);
                    }
                }
            }
        }
    }

    // Epilogue: y /= l, write fp16
    #pragma unroll
    for (int mm = 0; mm < 2; mm++) {
        const float i0 = 1.0f / l0[mm], i1 = 1.0f / l1[mm];
        const int grow0 = b * SS + qb * 128 + w * 32 + mm * 16 + g;
        #pragma unroll
        for (int nn = 0; nn < 8; nn++) {
            int col = h * HD + nn * 8 + 2 * tq;
            size_t idx0 = (size_t)grow0 * DD + col;
            size_t idx1 = (size_t)(grow0 + 8) * DD + col;
            *reinterpret_cast<uint32_t*>(y + idx0) =
                pack_f16x2(yacc[mm][nn][0] * i0, yacc[mm][nn][1] * i0);
            *reinterpret_cast<uint32_t*>(y + idx1) =
                pack_f16x2(yacc[mm][nn][2] * i1, yacc[mm][nn][3] * i1);
        }
    }
}

// ---------------------------------------------------------------------------
// Launch
// ---------------------------------------------------------------------------
extern "C" void kernel_launch(void* const* d_in, const int* in_sizes, int n_in,
                              void* d_out, int out_size)
{
    const float* x      = (const float*)d_in[0];
    const float* w_qkv  = (const float*)d_in[1];
    const float* w_proj = (const float*)d_in[2];
    float* out = (float*)d_out;

    __half *xh, *qkvh, *yh, *wqT, *wpT;
    cudaGetSymbolAddress((void**)&xh, g_xh);
    cudaGetSymbolAddress((void**)&qkvh, g_qkvh);
    cudaGetSymbolAddress((void**)&yh, g_yh);
    cudaGetSymbolAddress((void**)&wqT, g_wqkvT);
    cudaGetSymbolAddress((void**)&wpT, g_wprojT);

    cudaFuncSetAttribute(mma_gemm_kernel,
                         cudaFuncAttributeMaxDynamicSharedMemorySize, GEMM_SMEM);
    cudaFuncSetAttribute(mma_attn_kernel,
                         cudaFuncAttributeMaxDynamicSharedMemorySize, ATTN_SMEM);

    const int M = BB * SS;

    // conversions: 4096 (x) + 3072 (wqkv T) + 1024 (wproj T) blocks
    convert_kernel<<<4096 + 3072 + 1024, 256>>>(x, w_qkv, w_proj, xh, wqT, wpT);

    // qkv = x @ w_qkv -> fp16 (Q columns pre-scaled by 0.125)
    mma_gemm_kernel<<<dim3(3 * DD / 128, M / 128), 128, GEMM_SMEM>>>(
        xh, wqT, nullptr, qkvh, 3 * DD, DD);

    // attention -> y fp16
    mma_attn_kernel<<<dim3(SS / 128, BB * NH), 128, ATTN_SMEM>>>(qkvh, yh);

    // out = y @ w_proj -> fp32
    mma_gemm_kernel<<<dim3(DD / 128, M / 128), 128, GEMM_SMEM>>>(
        yh, wpT, out, nullptr, DD, DD);
}